// round 1
// baseline (speedup 1.0000x reference)
#include <cuda_runtime.h>
#include <cuda_bf16.h>
#include <cstdint>
#include <cstddef>

// Problem constants
constexpr int BATCH = 256;
constexpr int SEQ   = 512;
constexpr int INP   = 128;
constexpr int HID   = 256;
constexpr int G4H   = 1024;   // 4*HID

// Persistent kernel config
constexpr int GRID_P    = 128;   // 8 row-blocks x 16 unit-blocks (<=148 SMs -> co-resident)
constexpr int THREADS_P = 128;

// Dynamic smem layout (floats) for persistent kernel
constexpr int WS_OFF = 0;                    // Whh slice, k-major: [256][64]
constexpr int AS_OFF = WS_OFF + 256 * 64;    // h tile, k-major:    [256][32]
constexpr int GS_OFF = AS_OFF + 256 * 32;    // gates exchange:     [32][65] (padded)
constexpr int CS_OFF = GS_OFF + 32 * 65;     // cell state:         [32][17] (padded)
constexpr int SMEM_FLOATS = CS_OFF + 32 * 17;
constexpr size_t LSTM_SMEM = (size_t)SMEM_FLOATS * sizeof(float); // 108,800 B

// ---------------- scratch (device globals: allowed scratch mechanism) ----------------
__device__ float g_xpre[(size_t)BATCH * SEQ * G4H];  // 512 MB: input-projection pre-activations
__device__ float g_y0[(size_t)BATCH * SEQ * HID];    // 128 MB: layer-0 outputs
__device__ float g_h[2][BATCH * HID];                // double-buffered hidden state
__device__ unsigned int g_bar_count = 0;
__device__ unsigned int g_bar_gen   = 0;

// ---------------- grid-wide barrier (generation counting) ----------------
__device__ __forceinline__ void grid_sync()
{
    __syncthreads();
    if (threadIdx.x == 0) {
        __threadfence();  // release: make this CTA's (and, via syncthreads, block's) stores visible
        unsigned int gen  = *((volatile unsigned int*)&g_bar_gen);
        unsigned int prev = atomicAdd(&g_bar_count, 1u);
        if (prev == GRID_P - 1) {
            g_bar_count = 0;
            __threadfence();
            atomicAdd(&g_bar_gen, 1u);
        } else {
            while (*((volatile unsigned int*)&g_bar_gen) == gen) { }
            __threadfence();  // acquire
        }
    }
    __syncthreads();
}

__device__ __forceinline__ float sigmoidf_(float x)
{
    return 1.0f / (1.0f + __expf(-x));
}

// ---------------- big input-projection GEMM: C = A @ B^T + b1 + b2 -> g_xpre ----------------
// A: [M, K] row-major (K contiguous). B: [1024, K] row-major. C: [M, 1024] -> g_xpre.
// BM=BN=64, BK=32, 256 threads, 4x4 microtile, k-major transposed smem.
template<int K>
__global__ void __launch_bounds__(256)
gemm_nt_bias(const float* __restrict__ A, const float* __restrict__ Bm,
             const float* __restrict__ b1, const float* __restrict__ b2)
{
    __shared__ float As[32 * 64];
    __shared__ float Bs[32 * 64];

    const int tid = threadIdx.x;
    const size_t m0 = (size_t)blockIdx.y * 64;
    const int n0 = blockIdx.x * 64;
    const int tr = tid & 15;   // row group (x4)
    const int tc = tid >> 4;   // col group (x4)

    float acc[4][4] = {};

    for (int kc = 0; kc < K; kc += 32) {
        #pragma unroll
        for (int it = 0; it < 2; ++it) {
            int idx = tid + it * 256;      // 0..511
            int row = idx & 63;
            int kf  = idx >> 6;            // 0..7  (float4 index within 32-k chunk)
            float4 va = *reinterpret_cast<const float4*>(&A[(m0 + row) * K + kc + kf * 4]);
            As[(kf * 4 + 0) * 64 + row] = va.x;
            As[(kf * 4 + 1) * 64 + row] = va.y;
            As[(kf * 4 + 2) * 64 + row] = va.z;
            As[(kf * 4 + 3) * 64 + row] = va.w;
            float4 vb = *reinterpret_cast<const float4*>(&Bm[(size_t)(n0 + row) * K + kc + kf * 4]);
            Bs[(kf * 4 + 0) * 64 + row] = vb.x;
            Bs[(kf * 4 + 1) * 64 + row] = vb.y;
            Bs[(kf * 4 + 2) * 64 + row] = vb.z;
            Bs[(kf * 4 + 3) * 64 + row] = vb.w;
        }
        __syncthreads();

        #pragma unroll 8
        for (int k = 0; k < 32; ++k) {
            float4 a = *reinterpret_cast<const float4*>(&As[k * 64 + tr * 4]);
            float4 b = *reinterpret_cast<const float4*>(&Bs[k * 64 + tc * 4]);
            float av[4] = {a.x, a.y, a.z, a.w};
            float bv[4] = {b.x, b.y, b.z, b.w};
            #pragma unroll
            for (int i = 0; i < 4; ++i)
                #pragma unroll
                for (int j = 0; j < 4; ++j)
                    acc[i][j] += av[i] * bv[j];
        }
        __syncthreads();
    }

    float4 v1 = *reinterpret_cast<const float4*>(&b1[n0 + tc * 4]);
    float4 v2 = *reinterpret_cast<const float4*>(&b2[n0 + tc * 4]);
    float bb[4] = {v1.x + v2.x, v1.y + v2.y, v1.z + v2.z, v1.w + v2.w};

    #pragma unroll
    for (int i = 0; i < 4; ++i) {
        float4 o;
        o.x = acc[i][0] + bb[0];
        o.y = acc[i][1] + bb[1];
        o.z = acc[i][2] + bb[2];
        o.w = acc[i][3] + bb[3];
        *reinterpret_cast<float4*>(&g_xpre[(m0 + tr * 4 + i) * (size_t)G4H + n0 + tc * 4]) = o;
    }
}

// ---------------- persistent LSTM layer kernel ----------------
// CTA(bi,bu): rows [bi*32, +32), hidden units [bu*16, +16). Computes all 4 gates
// for its (row, unit) tile each step; Whh slice cached in smem for the whole loop;
// cell state c kept in smem; h double-buffered in global; 1 grid barrier per step.
__global__ void __launch_bounds__(THREADS_P, 1)
lstm_layer_kernel(const float* __restrict__ Whh,
                  float* __restrict__ y_out,
                  float* __restrict__ out_h,
                  float* __restrict__ out_c)
{
    extern __shared__ float sm[];
    float* Ws = sm + WS_OFF;   // [k=256][cc=64]   cc = gate*16 + uu
    float* As = sm + AS_OFF;   // [k=256][row=32]
    float* Gs = sm + GS_OFF;   // [row=32][65]
    float* Cs = sm + CS_OFF;   // [row=32][17]

    const int tid = threadIdx.x;
    const int bi  = blockIdx.x >> 4;   // 0..7
    const int bu  = blockIdx.x & 15;   // 0..15
    const int r0  = bi * 32;
    const int u0  = bu * 16;

    // Load Whh slice, k-major transposed (once for all 512 steps)
    #pragma unroll 4
    for (int it = 0; it < 32; ++it) {
        int idx = tid + it * THREADS_P;    // 0..4095 float4 positions
        int cc  = idx & 63;
        int kf  = idx >> 6;                // 0..63
        int g   = cc >> 4;
        int uu  = cc & 15;
        float4 w = *reinterpret_cast<const float4*>(&Whh[(size_t)(g * HID + u0 + uu) * HID + kf * 4]);
        Ws[(kf * 4 + 0) * 64 + cc] = w.x;
        Ws[(kf * 4 + 1) * 64 + cc] = w.y;
        Ws[(kf * 4 + 2) * 64 + cc] = w.z;
        Ws[(kf * 4 + 3) * 64 + cc] = w.w;
    }
    // Zero initial hidden state (this CTA's portion) and cell state
    for (int q = tid; q < 512; q += THREADS_P) {
        int r  = q & 31;
        int uu = q >> 5;
        __stcg(&g_h[0][(r0 + r) * HID + u0 + uu], 0.0f);
    }
    for (int q = tid; q < 32 * 17; q += THREADS_P) Cs[q] = 0.0f;
    grid_sync();

    const int tr    = tid & 7;    // GEMM row group (x4)
    const int tc    = tid >> 3;   // GEMM col group (x4), over 64 packed cols
    const int row_a = tid & 31;   // activation-phase row
    const int uub   = tid >> 5;   // activation-phase unit base (0..3)

    int cur = 0;
    for (int t = 0; t < SEQ; ++t) {
        // Load h tile [32 rows][256 k] transposed into As
        const float* hsrc = g_h[cur];
        #pragma unroll 4
        for (int it = 0; it < 16; ++it) {
            int idx = tid + it * THREADS_P;   // 0..2047 float4 positions
            int row = idx & 31;
            int kf  = idx >> 5;               // 0..63
            float4 h4 = __ldcg(reinterpret_cast<const float4*>(&hsrc[(r0 + row) * HID + kf * 4]));
            As[(kf * 4 + 0) * 32 + row] = h4.x;
            As[(kf * 4 + 1) * 32 + row] = h4.y;
            As[(kf * 4 + 2) * 32 + row] = h4.z;
            As[(kf * 4 + 3) * 32 + row] = h4.w;
        }
        __syncthreads();

        // Recurrent GEMM: 32x64 tile, K=256
        float acc[4][4] = {};
        #pragma unroll 8
        for (int k = 0; k < HID; ++k) {
            float4 a = *reinterpret_cast<const float4*>(&As[k * 32 + tr * 4]);
            float4 b = *reinterpret_cast<const float4*>(&Ws[k * 64 + tc * 4]);
            float av[4] = {a.x, a.y, a.z, a.w};
            float bv[4] = {b.x, b.y, b.z, b.w};
            #pragma unroll
            for (int i = 0; i < 4; ++i)
                #pragma unroll
                for (int j = 0; j < 4; ++j)
                    acc[i][j] += av[i] * bv[j];
        }

        // Prefetch xpre for the activation mapping (overlap with STS+sync)
        float xp[4][4];
        #pragma unroll
        for (int p = 0; p < 4; ++p) {
            int uu = p * 4 + uub;
            size_t base = ((size_t)(r0 + row_a) * SEQ + t) * G4H + u0 + uu;
            #pragma unroll
            for (int g = 0; g < 4; ++g)
                xp[p][g] = __ldg(&g_xpre[base + (size_t)g * HID]);
        }

        // Exchange gate partials through smem
        #pragma unroll
        for (int i = 0; i < 4; ++i)
            #pragma unroll
            for (int j = 0; j < 4; ++j)
                Gs[(tr * 4 + i) * 65 + tc * 4 + j] = acc[i][j];
        __syncthreads();

        // Activation phase: each thread owns 4 (row, unit) pairs
        float* hdst = g_h[cur ^ 1];
        #pragma unroll
        for (int p = 0; p < 4; ++p) {
            int uu = p * 4 + uub;
            float gi = Gs[row_a * 65 +      uu] + xp[p][0];
            float gf = Gs[row_a * 65 + 16 + uu] + xp[p][1];
            float gg = Gs[row_a * 65 + 32 + uu] + xp[p][2];
            float go = Gs[row_a * 65 + 48 + uu] + xp[p][3];
            float ig = sigmoidf_(gi);
            float fg = sigmoidf_(gf);
            float og = sigmoidf_(go);
            float gc = tanhf(gg);
            float c  = fg * Cs[row_a * 17 + uu] + ig * gc;
            float h  = og * tanhf(c);
            Cs[row_a * 17 + uu] = c;
            __stcg(&hdst[(r0 + row_a) * HID + u0 + uu], h);
            y_out[((size_t)(r0 + row_a) * SEQ + t) * HID + u0 + uu] = h;
            if (out_h != nullptr && t == SEQ - 1) {
                out_h[(r0 + row_a) * HID + u0 + uu] = h;
                out_c[(r0 + row_a) * HID + u0 + uu] = c;
            }
        }

        grid_sync();   // all h writes of step t visible before step t+1 reads
        cur ^= 1;
    }
}

// ---------------- launch ----------------
extern "C" void kernel_launch(void* const* d_in, const int* in_sizes, int n_in,
                              void* d_out, int out_size)
{
    const float* x    = (const float*)d_in[0];
    const float* Wih0 = (const float*)d_in[1];
    const float* Whh0 = (const float*)d_in[2];
    const float* bih0 = (const float*)d_in[3];
    const float* bhh0 = (const float*)d_in[4];
    const float* Wih1 = (const float*)d_in[5];
    const float* Whh1 = (const float*)d_in[6];
    const float* bih1 = (const float*)d_in[7];
    const float* bhh1 = (const float*)d_in[8];
    float* out = (float*)d_out;

    float* y0_ptr = nullptr;
    cudaGetSymbolAddress((void**)&y0_ptr, g_y0);
    cudaFuncSetAttribute(lstm_layer_kernel,
                         cudaFuncAttributeMaxDynamicSharedMemorySize, (int)LSTM_SMEM);

    dim3 ggrid(G4H / 64, (BATCH * SEQ) / 64);   // (16, 2048)

    // Layer 0: input projection (all timesteps), then recurrence
    gemm_nt_bias<INP><<<ggrid, 256>>>(x, Wih0, bih0, bhh0);
    lstm_layer_kernel<<<GRID_P, THREADS_P, LSTM_SMEM>>>(Whh0, y0_ptr, nullptr, nullptr);

    // Layer 1: input projection over layer-0 outputs, then recurrence -> d_out
    gemm_nt_bias<HID><<<ggrid, 256>>>(y0_ptr, Wih1, bih1, bhh1);
    float* out_h = out + (size_t)BATCH * SEQ * HID;
    float* out_c = out_h + (size_t)BATCH * HID;
    lstm_layer_kernel<<<GRID_P, THREADS_P, LSTM_SMEM>>>(Whh1, out, out_h, out_c);
}

// round 4
// speedup vs baseline: 1.1933x; 1.1933x over previous
#include <cuda_runtime.h>
#include <cuda_bf16.h>
#include <cstdint>
#include <cstddef>

// Problem constants
constexpr int BATCH = 256;
constexpr int SEQ   = 512;
constexpr int INP   = 128;
constexpr int HID   = 256;
constexpr int G4H   = 1024;   // 4*HID

// Persistent recurrent kernel config
constexpr int GRID_P    = 128;
constexpr int THREADS_P = 128;

// Dynamic smem layout (floats) for persistent kernel
constexpr int WS_OFF = 0;                    // Whh slice, k-major: [256][64]
constexpr int AS_OFF = WS_OFF + 256 * 64;    // h tile, k-major:    [256][32]
constexpr int GS_OFF = AS_OFF + 256 * 32;    // gates exchange:     [32][65]
constexpr int CS_OFF = GS_OFF + 32 * 65;     // cell state:         [32][17]
constexpr int SMEM_FLOATS = CS_OFF + 32 * 17;
constexpr size_t LSTM_SMEM = (size_t)SMEM_FLOATS * sizeof(float);

// ---------------- scratch ----------------
__device__ float g_xpre[(size_t)BATCH * SEQ * G4H];  // 512 MB
__device__ float g_y0[(size_t)BATCH * SEQ * HID];    // 128 MB
__device__ float g_h[2][BATCH * HID];
__device__ unsigned int g_bar_count = 0;
__device__ unsigned int g_bar_gen   = 0;

__device__ __forceinline__ uint32_t smem_u32(const void* p) {
    uint32_t a;
    asm("{ .reg .u64 t; cvta.to.shared.u64 t, %1; cvt.u32.u64 %0, t; }" : "=r"(a) : "l"(p));
    return a;
}

// ================= mma.sync helpers (baseline PTX, sm_80+) =================
__device__ __forceinline__ void ldmx4(uint32_t* r, uint32_t addr) {
    asm volatile("ldmatrix.sync.aligned.m8n8.x4.shared.b16 {%0,%1,%2,%3}, [%4];"
                 : "=r"(r[0]), "=r"(r[1]), "=r"(r[2]), "=r"(r[3]) : "r"(addr));
}
__device__ __forceinline__ void mma16816(float* d, const uint32_t* a,
                                         uint32_t b0, uint32_t b1) {
    asm volatile(
        "mma.sync.aligned.m16n8k16.row.col.f32.bf16.bf16.f32 "
        "{%0,%1,%2,%3}, {%4,%5,%6,%7}, {%8,%9}, {%0,%1,%2,%3};"
        : "+f"(d[0]), "+f"(d[1]), "+f"(d[2]), "+f"(d[3])
        : "r"(a[0]), "r"(a[1]), "r"(a[2]), "r"(a[3]), "r"(b0), "r"(b1));
}

__device__ __forceinline__ void cvt_pair8(const float* v, uint4& hi, uint4& lo) {
    unsigned hs[8], ls[8];
    #pragma unroll
    for (int j = 0; j < 8; ++j) {
        __nv_bfloat16 h = __float2bfloat16(v[j]);
        float hf = __bfloat162float(h);
        __nv_bfloat16 l = __float2bfloat16(v[j] - hf);
        hs[j] = (unsigned)__bfloat16_as_ushort(h);
        ls[j] = (unsigned)__bfloat16_as_ushort(l);
    }
    hi.x = hs[0] | (hs[1] << 16); hi.y = hs[2] | (hs[3] << 16);
    hi.z = hs[4] | (hs[5] << 16); hi.w = hs[6] | (hs[7] << 16);
    lo.x = ls[0] | (ls[1] << 16); lo.y = ls[2] | (ls[3] << 16);
    lo.z = ls[4] | (ls[5] << 16); lo.w = ls[6] | (ls[7] << 16);
}

// ================= input-projection GEMM on HMMA (mma.sync, bf16-pair) =================
// C[M,1024] = A[M,K] @ W[1024,K]^T + (b1+b2), fp32 accum.
// CTA tile 128(M) x 128(N), BK=32. 8 warps: 2(m) x 4(n) -> warp tile 64x32.
// smem planes (bf16, 80-byte row pitch = 40 bf16): Ah, Al, Bh, Bl.
constexpr int GM_THREADS = 256;
constexpr int PITCH = 80;                       // bytes per 32-element bf16 row
constexpr int PLANE = 128 * PITCH;              // 10240 B
constexpr int SB_BIAS = 0;                      // 512 B bias
constexpr int SB_AH = 1024;
constexpr int SB_AL = SB_AH + PLANE;
constexpr int SB_BH = SB_AL + PLANE;
constexpr int SB_BL = SB_BH + PLANE;
constexpr size_t GM_SMEM = SB_BL + PLANE;       // 41984 B

template<int K>
__global__ void __launch_bounds__(GM_THREADS)
gemm_mma(const float* __restrict__ A, const float* __restrict__ W,
         const float* __restrict__ b1, const float* __restrict__ b2,
         float* __restrict__ Cout)
{
    extern __shared__ char sm[];
    const uint32_t sbase = smem_u32(sm);
    float* sbias = (float*)(sm + SB_BIAS);

    const int tid  = threadIdx.x;
    const int lane = tid & 31;
    const int warp = tid >> 5;
    const int wm   = warp >> 2;          // 0..1  -> m offset wm*64
    const int wn   = warp & 3;           // 0..3  -> n offset wn*32
    const int n0   = blockIdx.x * 128;
    const size_t m0 = (size_t)blockIdx.y * 128;

    if (tid < 128) sbias[tid] = b1[n0 + tid] + b2[n0 + tid];

    // loader mapping: thread t -> row t/2, half t%2 (16 floats = 4 float4)
    const int lrow  = tid >> 1;
    const int lhalf = tid & 1;
    const float* gA = A + (m0 + lrow) * K + lhalf * 16;
    const float* gB = W + (size_t)(n0 + lrow) * K + lhalf * 16;

    float acc[4][4][4] = {};      // [mi][ni][frag]
    float ra[16], rb[16];

    // prefetch chunk 0
    #pragma unroll
    for (int q = 0; q < 4; ++q) {
        *(float4*)(ra + q * 4) = *(const float4*)(gA + q * 4);
        *(float4*)(rb + q * 4) = *(const float4*)(gB + q * 4);
    }

    constexpr int NC = K / 32;
    for (int c = 0; c < NC; ++c) {
        // convert + store current chunk to smem planes
        #pragma unroll
        for (int j = 0; j < 2; ++j) {
            uint4 hi, lo;
            uint32_t off = (uint32_t)(lrow * PITCH + lhalf * 32 + j * 16);
            cvt_pair8(ra + j * 8, hi, lo);
            *(uint4*)(sm + SB_AH + off) = hi;
            *(uint4*)(sm + SB_AL + off) = lo;
            cvt_pair8(rb + j * 8, hi, lo);
            *(uint4*)(sm + SB_BH + off) = hi;
            *(uint4*)(sm + SB_BL + off) = lo;
        }
        __syncthreads();

        // prefetch next chunk (LDG latency hidden behind MMAs)
        if (c + 1 < NC) {
            #pragma unroll
            for (int q = 0; q < 4; ++q) {
                *(float4*)(ra + q * 4) = *(const float4*)(gA + (c + 1) * 32 + q * 4);
                *(float4*)(rb + q * 4) = *(const float4*)(gB + (c + 1) * 32 + q * 4);
            }
        }

        // MMA over 2 k16 blocks
        #pragma unroll
        for (int kb = 0; kb < 2; ++kb) {
            uint32_t Ah[4][4], Al[4][4], Bh[2][4], Bl[2][4];
            const uint32_t acol = (uint32_t)(kb * 32 + (lane >> 4) * 16);
            #pragma unroll
            for (int mi = 0; mi < 4; ++mi) {
                uint32_t rowoff = (uint32_t)((wm * 64 + mi * 16 + (lane & 15)) * PITCH) + acol;
                ldmx4(Ah[mi], sbase + SB_AH + rowoff);
                ldmx4(Al[mi], sbase + SB_AL + rowoff);
            }
            const uint32_t bcol = (uint32_t)(kb * 32 + ((lane >> 3) & 1) * 16);
            #pragma unroll
            for (int nb = 0; nb < 2; ++nb) {
                uint32_t rowoff = (uint32_t)((wn * 32 + nb * 16 + (lane & 7) + ((lane >> 4) << 3)) * PITCH) + bcol;
                ldmx4(Bh[nb], sbase + SB_BH + rowoff);
                ldmx4(Bl[nb], sbase + SB_BL + rowoff);
            }
            #pragma unroll
            for (int mi = 0; mi < 4; ++mi) {
                #pragma unroll
                for (int ni = 0; ni < 4; ++ni) {
                    const int nb = ni >> 1, h = (ni & 1) * 2;
                    mma16816(acc[mi][ni], Ah[mi], Bh[nb][h], Bh[nb][h + 1]);
                    mma16816(acc[mi][ni], Ah[mi], Bl[nb][h], Bl[nb][h + 1]);
                    mma16816(acc[mi][ni], Al[mi], Bh[nb][h], Bh[nb][h + 1]);
                }
            }
        }
        __syncthreads();
    }

    // epilogue: bias + direct stores (float2 per fragment half)
    const int g   = lane >> 2;
    const int tig = lane & 3;
    #pragma unroll
    for (int mi = 0; mi < 4; ++mi) {
        const size_t row = m0 + wm * 64 + mi * 16 + g;
        float* dst0 = Cout + row * G4H + n0;
        float* dst8 = dst0 + (size_t)8 * G4H;
        #pragma unroll
        for (int ni = 0; ni < 4; ++ni) {
            const int col = wn * 32 + ni * 8 + tig * 2;
            const float bb0 = sbias[col], bb1 = sbias[col + 1];
            float2 v0 = {acc[mi][ni][0] + bb0, acc[mi][ni][1] + bb1};
            float2 v1 = {acc[mi][ni][2] + bb0, acc[mi][ni][3] + bb1};
            *(float2*)(dst0 + col) = v0;
            *(float2*)(dst8 + col) = v1;
        }
    }
}

// ================= grid-wide barrier =================
__device__ __forceinline__ void grid_sync()
{
    __syncthreads();
    if (threadIdx.x == 0) {
        __threadfence();
        unsigned int gen  = *((volatile unsigned int*)&g_bar_gen);
        unsigned int prev = atomicAdd(&g_bar_count, 1u);
        if (prev == GRID_P - 1) {
            g_bar_count = 0;
            __threadfence();
            atomicAdd(&g_bar_gen, 1u);
        } else {
            while (*((volatile unsigned int*)&g_bar_gen) == gen) { }
            __threadfence();
        }
    }
    __syncthreads();
}

__device__ __forceinline__ float sigmoidf_(float x) { return 1.0f / (1.0f + __expf(-x)); }

// ================= persistent LSTM recurrence (unchanged, known-good) =================
__global__ void __launch_bounds__(THREADS_P, 1)
lstm_layer_kernel(const float* __restrict__ Whh,
                  float* __restrict__ y_out,
                  float* __restrict__ out_h,
                  float* __restrict__ out_c)
{
    extern __shared__ float smf[];
    float* Ws = smf + WS_OFF;
    float* As = smf + AS_OFF;
    float* Gs = smf + GS_OFF;
    float* Cs = smf + CS_OFF;

    const int tid = threadIdx.x;
    const int bi  = blockIdx.x >> 4;
    const int bu  = blockIdx.x & 15;
    const int r0  = bi * 32;
    const int u0  = bu * 16;

    #pragma unroll 4
    for (int it = 0; it < 32; ++it) {
        int idx = tid + it * THREADS_P;
        int cc  = idx & 63;
        int kf  = idx >> 6;
        int g   = cc >> 4;
        int uu  = cc & 15;
        float4 w = *reinterpret_cast<const float4*>(&Whh[(size_t)(g * HID + u0 + uu) * HID + kf * 4]);
        Ws[(kf * 4 + 0) * 64 + cc] = w.x;
        Ws[(kf * 4 + 1) * 64 + cc] = w.y;
        Ws[(kf * 4 + 2) * 64 + cc] = w.z;
        Ws[(kf * 4 + 3) * 64 + cc] = w.w;
    }
    for (int q = tid; q < 512; q += THREADS_P) {
        int r  = q & 31;
        int uu = q >> 5;
        __stcg(&g_h[0][(r0 + r) * HID + u0 + uu], 0.0f);
    }
    for (int q = tid; q < 32 * 17; q += THREADS_P) Cs[q] = 0.0f;
    grid_sync();

    const int tr    = tid & 7;
    const int tc    = tid >> 3;
    const int row_a = tid & 31;
    const int uub   = tid >> 5;

    int cur = 0;
    for (int t = 0; t < SEQ; ++t) {
        const float* hsrc = g_h[cur];
        #pragma unroll 4
        for (int it = 0; it < 16; ++it) {
            int idx = tid + it * THREADS_P;
            int row = idx & 31;
            int kf  = idx >> 5;
            float4 h4 = __ldcg(reinterpret_cast<const float4*>(&hsrc[(r0 + row) * HID + kf * 4]));
            As[(kf * 4 + 0) * 32 + row] = h4.x;
            As[(kf * 4 + 1) * 32 + row] = h4.y;
            As[(kf * 4 + 2) * 32 + row] = h4.z;
            As[(kf * 4 + 3) * 32 + row] = h4.w;
        }
        __syncthreads();

        float acc[4][4] = {};
        #pragma unroll 8
        for (int k = 0; k < HID; ++k) {
            float4 a = *reinterpret_cast<const float4*>(&As[k * 32 + tr * 4]);
            float4 b = *reinterpret_cast<const float4*>(&Ws[k * 64 + tc * 4]);
            float av[4] = {a.x, a.y, a.z, a.w};
            float bv[4] = {b.x, b.y, b.z, b.w};
            #pragma unroll
            for (int i = 0; i < 4; ++i)
                #pragma unroll
                for (int j = 0; j < 4; ++j)
                    acc[i][j] += av[i] * bv[j];
        }

        float xp[4][4];
        #pragma unroll
        for (int p = 0; p < 4; ++p) {
            int uu = p * 4 + uub;
            size_t base = ((size_t)(r0 + row_a) * SEQ + t) * G4H + u0 + uu;
            #pragma unroll
            for (int g = 0; g < 4; ++g)
                xp[p][g] = __ldg(&g_xpre[base + (size_t)g * HID]);
        }

        #pragma unroll
        for (int i = 0; i < 4; ++i)
            #pragma unroll
            for (int j = 0; j < 4; ++j)
                Gs[(tr * 4 + i) * 65 + tc * 4 + j] = acc[i][j];
        __syncthreads();

        float* hdst = g_h[cur ^ 1];
        #pragma unroll
        for (int p = 0; p < 4; ++p) {
            int uu = p * 4 + uub;
            float gi = Gs[row_a * 65 +      uu] + xp[p][0];
            float gf = Gs[row_a * 65 + 16 + uu] + xp[p][1];
            float gg = Gs[row_a * 65 + 32 + uu] + xp[p][2];
            float go = Gs[row_a * 65 + 48 + uu] + xp[p][3];
            float ig = sigmoidf_(gi);
            float fg = sigmoidf_(gf);
            float og = sigmoidf_(go);
            float gc = tanhf(gg);
            float c  = fg * Cs[row_a * 17 + uu] + ig * gc;
            float h  = og * tanhf(c);
            Cs[row_a * 17 + uu] = c;
            __stcg(&hdst[(r0 + row_a) * HID + u0 + uu], h);
            y_out[((size_t)(r0 + row_a) * SEQ + t) * HID + u0 + uu] = h;
            if (out_h != nullptr && t == SEQ - 1) {
                out_h[(r0 + row_a) * HID + u0 + uu] = h;
                out_c[(r0 + row_a) * HID + u0 + uu] = c;
            }
        }

        grid_sync();
        cur ^= 1;
    }
}

// ================= launch =================
extern "C" void kernel_launch(void* const* d_in, const int* in_sizes, int n_in,
                              void* d_out, int out_size)
{
    const float* x    = (const float*)d_in[0];
    const float* Wih0 = (const float*)d_in[1];
    const float* Whh0 = (const float*)d_in[2];
    const float* bih0 = (const float*)d_in[3];
    const float* bhh0 = (const float*)d_in[4];
    const float* Wih1 = (const float*)d_in[5];
    const float* Whh1 = (const float*)d_in[6];
    const float* bih1 = (const float*)d_in[7];
    const float* bhh1 = (const float*)d_in[8];
    float* out = (float*)d_out;

    float* y0_ptr = nullptr;
    float* xpre_ptr = nullptr;
    cudaGetSymbolAddress((void**)&y0_ptr, g_y0);
    cudaGetSymbolAddress((void**)&xpre_ptr, g_xpre);

    cudaFuncSetAttribute(lstm_layer_kernel,
                         cudaFuncAttributeMaxDynamicSharedMemorySize, (int)LSTM_SMEM);
    cudaFuncSetAttribute(gemm_mma<INP>,
                         cudaFuncAttributeMaxDynamicSharedMemorySize, (int)GM_SMEM);
    cudaFuncSetAttribute(gemm_mma<HID>,
                         cudaFuncAttributeMaxDynamicSharedMemorySize, (int)GM_SMEM);

    dim3 tgrid(G4H / 128, (BATCH * SEQ) / 128);   // (8, 1024)

    // Layer 0
    gemm_mma<INP><<<tgrid, GM_THREADS, GM_SMEM>>>(x, Wih0, bih0, bhh0, xpre_ptr);
    lstm_layer_kernel<<<GRID_P, THREADS_P, LSTM_SMEM>>>(Whh0, y0_ptr, nullptr, nullptr);

    // Layer 1
    gemm_mma<HID><<<tgrid, GM_THREADS, GM_SMEM>>>(y0_ptr, Wih1, bih1, bhh1, xpre_ptr);
    float* out_h = out + (size_t)BATCH * SEQ * HID;
    float* out_c = out_h + (size_t)BATCH * HID;
    lstm_layer_kernel<<<GRID_P, THREADS_P, LSTM_SMEM>>>(Whh1, out, out_h, out_c);
}

// round 7
// speedup vs baseline: 2.1349x; 1.7890x over previous
#include <cuda_runtime.h>
#include <cuda_bf16.h>
#include <cstdint>
#include <cstddef>

// Problem constants
constexpr int BATCH = 256;
constexpr int SEQ   = 512;
constexpr int INP   = 128;
constexpr int HID   = 256;
constexpr int G4H   = 1024;   // 4*HID

// Persistent recurrent kernel config
constexpr int GRID_P    = 128;   // 8 row-blocks x 16 unit-blocks, co-resident
constexpr int THREADS_P = 128;

// ---------------- scratch ----------------
__device__ float g_xpre[(size_t)BATCH * SEQ * G4H];        // 512 MB
__device__ float g_y0[(size_t)BATCH * SEQ * HID];          // 128 MB
__device__ __nv_bfloat16 g_hbf[2][2][BATCH * HID];         // [buf][hi/lo][B*H]
__device__ unsigned int g_bar_count = 0;
__device__ unsigned int g_bar_gen   = 0;

__device__ __forceinline__ uint32_t smem_u32(const void* p) {
    uint32_t a;
    asm("{ .reg .u64 t; cvta.to.shared.u64 t, %1; cvt.u32.u64 %0, t; }" : "=r"(a) : "l"(p));
    return a;
}

// ================= mma.sync helpers (baseline PTX, sm_80+) =================
__device__ __forceinline__ void ldmx4(uint32_t* r, uint32_t addr) {
    asm volatile("ldmatrix.sync.aligned.m8n8.x4.shared.b16 {%0,%1,%2,%3}, [%4];"
                 : "=r"(r[0]), "=r"(r[1]), "=r"(r[2]), "=r"(r[3]) : "r"(addr));
}
__device__ __forceinline__ void mma16816(float* d, const uint32_t* a,
                                         uint32_t b0, uint32_t b1) {
    asm volatile(
        "mma.sync.aligned.m16n8k16.row.col.f32.bf16.bf16.f32 "
        "{%0,%1,%2,%3}, {%4,%5,%6,%7}, {%8,%9}, {%0,%1,%2,%3};"
        : "+f"(d[0]), "+f"(d[1]), "+f"(d[2]), "+f"(d[3])
        : "r"(a[0]), "r"(a[1]), "r"(a[2]), "r"(a[3]), "r"(b0), "r"(b1));
}

__device__ __forceinline__ void cvt_pair8(const float* v, uint4& hi, uint4& lo) {
    unsigned hs[8], ls[8];
    #pragma unroll
    for (int j = 0; j < 8; ++j) {
        __nv_bfloat16 h = __float2bfloat16(v[j]);
        float hf = __bfloat162float(h);
        __nv_bfloat16 l = __float2bfloat16(v[j] - hf);
        hs[j] = (unsigned)__bfloat16_as_ushort(h);
        ls[j] = (unsigned)__bfloat16_as_ushort(l);
    }
    hi.x = hs[0] | (hs[1] << 16); hi.y = hs[2] | (hs[3] << 16);
    hi.z = hs[4] | (hs[5] << 16); hi.w = hs[6] | (hs[7] << 16);
    lo.x = ls[0] | (ls[1] << 16); lo.y = ls[2] | (ls[3] << 16);
    lo.z = ls[4] | (ls[5] << 16); lo.w = ls[6] | (ls[7] << 16);
}
__device__ __forceinline__ void cvt_pair4(float4 v, uint2& hi, uint2& lo) {
    float f[4] = {v.x, v.y, v.z, v.w};
    unsigned hs[4], ls[4];
    #pragma unroll
    for (int j = 0; j < 4; ++j) {
        __nv_bfloat16 h = __float2bfloat16(f[j]);
        float hf = __bfloat162float(h);
        __nv_bfloat16 l = __float2bfloat16(f[j] - hf);
        hs[j] = (unsigned)__bfloat16_as_ushort(h);
        ls[j] = (unsigned)__bfloat16_as_ushort(l);
    }
    hi.x = hs[0] | (hs[1] << 16); hi.y = hs[2] | (hs[3] << 16);
    lo.x = ls[0] | (ls[1] << 16); lo.y = ls[2] | (ls[3] << 16);
}

// ================= input-projection GEMM on HMMA (unchanged, validated R4) =================
constexpr int GM_THREADS = 256;
constexpr int PITCH = 80;
constexpr int PLANE = 128 * PITCH;
constexpr int SB_BIAS = 0;
constexpr int SB_AH = 1024;
constexpr int SB_AL = SB_AH + PLANE;
constexpr int SB_BH = SB_AL + PLANE;
constexpr int SB_BL = SB_BH + PLANE;
constexpr size_t GM_SMEM = SB_BL + PLANE;

template<int K>
__global__ void __launch_bounds__(GM_THREADS)
gemm_mma(const float* __restrict__ A, const float* __restrict__ W,
         const float* __restrict__ b1, const float* __restrict__ b2,
         float* __restrict__ Cout)
{
    extern __shared__ char sm[];
    const uint32_t sbase = smem_u32(sm);
    float* sbias = (float*)(sm + SB_BIAS);

    const int tid  = threadIdx.x;
    const int lane = tid & 31;
    const int warp = tid >> 5;
    const int wm   = warp >> 2;
    const int wn   = warp & 3;
    const int n0   = blockIdx.x * 128;
    const size_t m0 = (size_t)blockIdx.y * 128;

    if (tid < 128) sbias[tid] = b1[n0 + tid] + b2[n0 + tid];

    const int lrow  = tid >> 1;
    const int lhalf = tid & 1;
    const float* gA = A + (m0 + lrow) * K + lhalf * 16;
    const float* gB = W + (size_t)(n0 + lrow) * K + lhalf * 16;

    float acc[4][4][4] = {};
    float ra[16], rb[16];

    #pragma unroll
    for (int q = 0; q < 4; ++q) {
        *(float4*)(ra + q * 4) = *(const float4*)(gA + q * 4);
        *(float4*)(rb + q * 4) = *(const float4*)(gB + q * 4);
    }

    constexpr int NC = K / 32;
    for (int c = 0; c < NC; ++c) {
        #pragma unroll
        for (int j = 0; j < 2; ++j) {
            uint4 hi, lo;
            uint32_t off = (uint32_t)(lrow * PITCH + lhalf * 32 + j * 16);
            cvt_pair8(ra + j * 8, hi, lo);
            *(uint4*)(sm + SB_AH + off) = hi;
            *(uint4*)(sm + SB_AL + off) = lo;
            cvt_pair8(rb + j * 8, hi, lo);
            *(uint4*)(sm + SB_BH + off) = hi;
            *(uint4*)(sm + SB_BL + off) = lo;
        }
        __syncthreads();

        if (c + 1 < NC) {
            #pragma unroll
            for (int q = 0; q < 4; ++q) {
                *(float4*)(ra + q * 4) = *(const float4*)(gA + (c + 1) * 32 + q * 4);
                *(float4*)(rb + q * 4) = *(const float4*)(gB + (c + 1) * 32 + q * 4);
            }
        }

        #pragma unroll
        for (int kb = 0; kb < 2; ++kb) {
            uint32_t Ah[4][4], Al[4][4], Bh[2][4], Bl[2][4];
            const uint32_t acol = (uint32_t)(kb * 32 + (lane >> 4) * 16);
            #pragma unroll
            for (int mi = 0; mi < 4; ++mi) {
                uint32_t rowoff = (uint32_t)((wm * 64 + mi * 16 + (lane & 15)) * PITCH) + acol;
                ldmx4(Ah[mi], sbase + SB_AH + rowoff);
                ldmx4(Al[mi], sbase + SB_AL + rowoff);
            }
            const uint32_t bcol = (uint32_t)(kb * 32 + ((lane >> 3) & 1) * 16);
            #pragma unroll
            for (int nb = 0; nb < 2; ++nb) {
                uint32_t rowoff = (uint32_t)((wn * 32 + nb * 16 + (lane & 7) + ((lane >> 4) << 3)) * PITCH) + bcol;
                ldmx4(Bh[nb], sbase + SB_BH + rowoff);
                ldmx4(Bl[nb], sbase + SB_BL + rowoff);
            }
            #pragma unroll
            for (int mi = 0; mi < 4; ++mi) {
                #pragma unroll
                for (int ni = 0; ni < 4; ++ni) {
                    const int nb = ni >> 1, h = (ni & 1) * 2;
                    mma16816(acc[mi][ni], Ah[mi], Bh[nb][h], Bh[nb][h + 1]);
                    mma16816(acc[mi][ni], Ah[mi], Bl[nb][h], Bl[nb][h + 1]);
                    mma16816(acc[mi][ni], Al[mi], Bh[nb][h], Bh[nb][h + 1]);
                }
            }
        }
        __syncthreads();
    }

    const int g   = lane >> 2;
    const int tig = lane & 3;
    #pragma unroll
    for (int mi = 0; mi < 4; ++mi) {
        const size_t row = m0 + wm * 64 + mi * 16 + g;
        float* dst0 = Cout + row * G4H + n0;
        float* dst8 = dst0 + (size_t)8 * G4H;
        #pragma unroll
        for (int ni = 0; ni < 4; ++ni) {
            const int col = wn * 32 + ni * 8 + tig * 2;
            const float bb0 = sbias[col], bb1 = sbias[col + 1];
            float2 v0 = {acc[mi][ni][0] + bb0, acc[mi][ni][1] + bb1};
            float2 v1 = {acc[mi][ni][2] + bb0, acc[mi][ni][3] + bb1};
            *(float2*)(dst0 + col) = v0;
            *(float2*)(dst8 + col) = v1;
        }
    }
}

// ================= grid-wide barrier =================
__device__ __forceinline__ void grid_sync()
{
    __syncthreads();
    if (threadIdx.x == 0) {
        __threadfence();
        unsigned int gen  = *((volatile unsigned int*)&g_bar_gen);
        unsigned int prev = atomicAdd(&g_bar_count, 1u);
        if (prev == GRID_P - 1) {
            g_bar_count = 0;
            __threadfence();
            atomicAdd(&g_bar_gen, 1u);
        } else {
            while (*((volatile unsigned int*)&g_bar_gen) == gen) { }
            __threadfence();
        }
    }
    __syncthreads();
}

__device__ __forceinline__ float sigmoidf_(float x) { return 1.0f / (1.0f + __expf(-x)); }

// ================= persistent LSTM recurrence (mma.sync bf16-pair) =================
// CTA(bi,bu): rows [bi*32,+32), units [bu*16,+16)  => gate-cols cc = g4*16+uu, 64 total.
// Whh slice resident in SMEM as bf16 hi/lo planes (pitch 528 B = 33 chunks, conflict-free).
// h double-buffered in global as bf16 hi/lo planes, written by the activation phase.
constexpr int RPITCH = 528;                       // bytes per 256-bf16 row
constexpr int R_WH_HI = 0;                        // 64*528
constexpr int R_WH_LO = R_WH_HI + 64 * RPITCH;
constexpr int R_AH    = R_WH_LO + 64 * RPITCH;    // 32*528
constexpr int R_AL    = R_AH + 32 * RPITCH;
constexpr int R_GS    = R_AL + 32 * RPITCH;       // 32 x 66 floats
constexpr int R_CS    = R_GS + 32 * 66 * 4;       // 32 x 17 floats
constexpr size_t R_SMEM = (size_t)R_CS + 32 * 17 * 4;   // 112,000 B

__global__ void __launch_bounds__(THREADS_P, 1)
lstm_layer_kernel(const float* __restrict__ Whh,
                  float* __restrict__ y_out,
                  float* __restrict__ out_h,
                  float* __restrict__ out_c)
{
    extern __shared__ char smr[];
    const uint32_t sbase = smem_u32(smr);
    float* Gs = (float*)(smr + R_GS);
    float* Cs = (float*)(smr + R_CS);

    const int tid  = threadIdx.x;
    const int lane = tid & 31;
    const int w    = tid >> 5;          // warp 0..3  (handles gate w, all 16 units)
    const int bi   = blockIdx.x >> 4;
    const int bu   = blockIdx.x & 15;
    const int r0   = bi * 32;
    const int u0   = bu * 16;

    // ---- prologue: convert Whh slice to bf16 pair, pitched ----
    #pragma unroll 4
    for (int it = 0; it < 32; ++it) {
        int idx = tid + it * THREADS_P;      // 0..4095 float4s
        int cc  = idx >> 6;                  // 0..63
        int kf  = idx & 63;                  // float4 within row
        int g4  = cc >> 4, uu = cc & 15;
        float4 v = *(const float4*)(&Whh[(size_t)(g4 * HID + u0 + uu) * HID + kf * 4]);
        uint2 hi, lo; cvt_pair4(v, hi, lo);
        *(uint2*)(smr + R_WH_HI + cc * RPITCH + kf * 8) = hi;
        *(uint2*)(smr + R_WH_LO + cc * RPITCH + kf * 8) = lo;
    }
    // zero h (this CTA's unit-slice of its rows) and cell state
    for (int q = tid; q < 512; q += THREADS_P) {
        int r = q & 31, uu = q >> 5;
        g_hbf[0][0][(r0 + r) * HID + u0 + uu] = __float2bfloat16(0.0f);
        g_hbf[0][1][(r0 + r) * HID + u0 + uu] = __float2bfloat16(0.0f);
    }
    for (int q = tid; q < 32 * 17; q += THREADS_P) Cs[q] = 0.0f;
    grid_sync();

    const int gq  = lane >> 2;          // C-fragment row group
    const int tig = lane & 3;
    const int row_a = tid & 31;         // activation row
    const int ug    = tid >> 5;         // activation unit group: units ug*4..+3

    int cur = 0;
    for (int t = 0; t < SEQ; ++t) {
        // ---- load h tile (bf16 pair) into SMEM ----
        const __nv_bfloat16* hhi = g_hbf[cur][0];
        const __nv_bfloat16* hlo = g_hbf[cur][1];
        #pragma unroll
        for (int it = 0; it < 8; ++it) {
            int idx = tid + it * THREADS_P;   // 0..1023 chunks of 16B
            int row = idx >> 5, ch = idx & 31;
            uint4 v = __ldcg((const uint4*)(hhi + (r0 + row) * HID) + ch);
            *(uint4*)(smr + R_AH + row * RPITCH + ch * 16) = v;
            v = __ldcg((const uint4*)(hlo + (r0 + row) * HID) + ch);
            *(uint4*)(smr + R_AL + row * RPITCH + ch * 16) = v;
        }
        __syncthreads();

        // ---- prefetch xpre (LDG.128 x4), overlaps with MMA ----
        float xv[4][4];
        {
            size_t base = ((size_t)(r0 + row_a) * SEQ + t) * G4H + u0 + ug * 4;
            #pragma unroll
            for (int g4 = 0; g4 < 4; ++g4) {
                float4 f = *(const float4*)(&g_xpre[base + (size_t)g4 * HID]);
                xv[g4][0] = f.x; xv[g4][1] = f.y; xv[g4][2] = f.z; xv[g4][3] = f.w;
            }
        }

        // ---- recurrent GEMM: 32(m) x 16(n per warp), K=256, bf16-pair ----
        float acc[2][2][4] = {};
        #pragma unroll 4
        for (int kb = 0; kb < 16; ++kb) {
            uint32_t Ahf[2][4], Alf[2][4], Bhf[4], Blf[4];
            const uint32_t acol = (uint32_t)(kb * 32 + (lane >> 4) * 16);
            #pragma unroll
            for (int mi = 0; mi < 2; ++mi) {
                uint32_t ro = (uint32_t)((mi * 16 + (lane & 15)) * RPITCH) + acol;
                ldmx4(Ahf[mi], sbase + R_AH + ro);
                ldmx4(Alf[mi], sbase + R_AL + ro);
            }
            const uint32_t brow = (uint32_t)(w * 16 + (lane & 7) + ((lane >> 4) << 3));
            const uint32_t bcol = (uint32_t)(kb * 32 + ((lane >> 3) & 1) * 16);
            ldmx4(Bhf, sbase + R_WH_HI + brow * RPITCH + bcol);
            ldmx4(Blf, sbase + R_WH_LO + brow * RPITCH + bcol);
            #pragma unroll
            for (int mi = 0; mi < 2; ++mi) {
                #pragma unroll
                for (int ni = 0; ni < 2; ++ni) {
                    const int h2 = ni * 2;
                    mma16816(acc[mi][ni], Ahf[mi], Bhf[h2], Bhf[h2 + 1]);
                    mma16816(acc[mi][ni], Ahf[mi], Blf[h2], Blf[h2 + 1]);
                    mma16816(acc[mi][ni], Alf[mi], Bhf[h2], Bhf[h2 + 1]);
                }
            }
        }

        // ---- store C fragments to Gs (pitch 66 floats) ----
        #pragma unroll
        for (int mi = 0; mi < 2; ++mi) {
            #pragma unroll
            for (int ni = 0; ni < 2; ++ni) {
                const int col = w * 16 + ni * 8 + tig * 2;
                float2 v0 = {acc[mi][ni][0], acc[mi][ni][1]};
                float2 v1 = {acc[mi][ni][2], acc[mi][ni][3]};
                *(float2*)(&Gs[(mi * 16 + gq) * 66 + col])     = v0;
                *(float2*)(&Gs[(mi * 16 + gq + 8) * 66 + col]) = v1;
            }
        }
        __syncthreads();

        // ---- activations: thread owns (row_a, units ug*4..+3) ----
        __nv_bfloat16* dhi = g_hbf[cur ^ 1][0];
        __nv_bfloat16* dlo = g_hbf[cur ^ 1][1];
        unsigned hh[4], hl[4];
        float4 yv, cv;
        float* ys = (float*)&yv;
        float* cs4 = (float*)&cv;
        #pragma unroll
        for (int j = 0; j < 4; ++j) {
            int uu = ug * 4 + j;
            float gi = Gs[row_a * 66 +      uu] + xv[0][j];
            float gf = Gs[row_a * 66 + 16 + uu] + xv[1][j];
            float gg = Gs[row_a * 66 + 32 + uu] + xv[2][j];
            float go = Gs[row_a * 66 + 48 + uu] + xv[3][j];
            float ig = sigmoidf_(gi);
            float fg = sigmoidf_(gf);
            float og = sigmoidf_(go);
            float gc = tanhf(gg);
            float c  = fg * Cs[row_a * 17 + uu] + ig * gc;
            float h  = og * tanhf(c);
            Cs[row_a * 17 + uu] = c;
            __nv_bfloat16 hb = __float2bfloat16(h);
            float hf = __bfloat162float(hb);
            __nv_bfloat16 lb = __float2bfloat16(h - hf);
            hh[j] = (unsigned)__bfloat16_as_ushort(hb);
            hl[j] = (unsigned)__bfloat16_as_ushort(lb);
            ys[j] = h;
            cs4[j] = c;
        }
        {
            const int uoff = (r0 + row_a) * HID + u0 + ug * 4;
            uint2 ph = {hh[0] | (hh[1] << 16), hh[2] | (hh[3] << 16)};
            uint2 pl = {hl[0] | (hl[1] << 16), hl[2] | (hl[3] << 16)};
            *(uint2*)(dhi + uoff) = ph;
            *(uint2*)(dlo + uoff) = pl;
            *(float4*)(&y_out[((size_t)(r0 + row_a) * SEQ + t) * HID + u0 + ug * 4]) = yv;
            if (out_h != nullptr && t == SEQ - 1) {
                *(float4*)(&out_h[uoff]) = yv;
                *(float4*)(&out_c[uoff]) = cv;
            }
        }

        grid_sync();
        cur ^= 1;
    }
}

// ================= launch =================
extern "C" void kernel_launch(void* const* d_in, const int* in_sizes, int n_in,
                              void* d_out, int out_size)
{
    const float* x    = (const float*)d_in[0];
    const float* Wih0 = (const float*)d_in[1];
    const float* Whh0 = (const float*)d_in[2];
    const float* bih0 = (const float*)d_in[3];
    const float* bhh0 = (const float*)d_in[4];
    const float* Wih1 = (const float*)d_in[5];
    const float* Whh1 = (const float*)d_in[6];
    const float* bih1 = (const float*)d_in[7];
    const float* bhh1 = (const float*)d_in[8];
    float* out = (float*)d_out;

    float* y0_ptr = nullptr;
    float* xpre_ptr = nullptr;
    cudaGetSymbolAddress((void**)&y0_ptr, g_y0);
    cudaGetSymbolAddress((void**)&xpre_ptr, g_xpre);

    cudaFuncSetAttribute(lstm_layer_kernel,
                         cudaFuncAttributeMaxDynamicSharedMemorySize, (int)R_SMEM);
    cudaFuncSetAttribute(gemm_mma<INP>,
                         cudaFuncAttributeMaxDynamicSharedMemorySize, (int)GM_SMEM);
    cudaFuncSetAttribute(gemm_mma<HID>,
                         cudaFuncAttributeMaxDynamicSharedMemorySize, (int)GM_SMEM);

    dim3 tgrid(G4H / 128, (BATCH * SEQ) / 128);   // (8, 1024)

    // Layer 0
    gemm_mma<INP><<<tgrid, GM_THREADS, GM_SMEM>>>(x, Wih0, bih0, bhh0, xpre_ptr);
    lstm_layer_kernel<<<GRID_P, THREADS_P, R_SMEM>>>(Whh0, y0_ptr, nullptr, nullptr);

    // Layer 1
    gemm_mma<HID><<<tgrid, GM_THREADS, GM_SMEM>>>(y0_ptr, Wih1, bih1, bhh1, xpre_ptr);
    float* out_h = out + (size_t)BATCH * SEQ * HID;
    float* out_c = out_h + (size_t)BATCH * HID;
    lstm_layer_kernel<<<GRID_P, THREADS_P, R_SMEM>>>(Whh1, out, out_h, out_c);
}

// round 8
// speedup vs baseline: 2.1536x; 1.0088x over previous
#include <cuda_runtime.h>
#include <cuda_bf16.h>
#include <cstdint>
#include <cstddef>

// Problem constants
constexpr int BATCH = 256;
constexpr int SEQ   = 512;
constexpr int INP   = 128;
constexpr int HID   = 256;
constexpr int G4H   = 1024;   // 4*HID

// Persistent recurrent kernel config
constexpr int GRID_P    = 128;   // 8 row-blocks x 16 unit-blocks, co-resident
constexpr int THREADS_P = 128;
constexpr int GROUP_CTAS = 16;   // CTAs per row-block sync group

// ---------------- scratch ----------------
__device__ float g_xpre[(size_t)BATCH * SEQ * G4H];        // 512 MB
__device__ float g_y0[(size_t)BATCH * SEQ * HID];          // 128 MB
__device__ __nv_bfloat16 g_hbf[2][2][BATCH * HID];         // [buf][hi/lo][B*H]
// per-row-group barrier state, 256B padding between groups (no L2 line sharing)
__device__ unsigned int g_grp_count[8][64];
__device__ unsigned int g_grp_gen[8][64];

__device__ __forceinline__ uint32_t smem_u32(const void* p) {
    uint32_t a;
    asm("{ .reg .u64 t; cvta.to.shared.u64 t, %1; cvt.u32.u64 %0, t; }" : "=r"(a) : "l"(p));
    return a;
}

// ================= mma.sync helpers (baseline PTX, sm_80+) =================
__device__ __forceinline__ void ldmx4(uint32_t* r, uint32_t addr) {
    asm volatile("ldmatrix.sync.aligned.m8n8.x4.shared.b16 {%0,%1,%2,%3}, [%4];"
                 : "=r"(r[0]), "=r"(r[1]), "=r"(r[2]), "=r"(r[3]) : "r"(addr));
}
__device__ __forceinline__ void mma16816(float* d, const uint32_t* a,
                                         uint32_t b0, uint32_t b1) {
    asm volatile(
        "mma.sync.aligned.m16n8k16.row.col.f32.bf16.bf16.f32 "
        "{%0,%1,%2,%3}, {%4,%5,%6,%7}, {%8,%9}, {%0,%1,%2,%3};"
        : "+f"(d[0]), "+f"(d[1]), "+f"(d[2]), "+f"(d[3])
        : "r"(a[0]), "r"(a[1]), "r"(a[2]), "r"(a[3]), "r"(b0), "r"(b1));
}

__device__ __forceinline__ void cvt_pair8(const float* v, uint4& hi, uint4& lo) {
    unsigned hs[8], ls[8];
    #pragma unroll
    for (int j = 0; j < 8; ++j) {
        __nv_bfloat16 h = __float2bfloat16(v[j]);
        float hf = __bfloat162float(h);
        __nv_bfloat16 l = __float2bfloat16(v[j] - hf);
        hs[j] = (unsigned)__bfloat16_as_ushort(h);
        ls[j] = (unsigned)__bfloat16_as_ushort(l);
    }
    hi.x = hs[0] | (hs[1] << 16); hi.y = hs[2] | (hs[3] << 16);
    hi.z = hs[4] | (hs[5] << 16); hi.w = hs[6] | (hs[7] << 16);
    lo.x = ls[0] | (ls[1] << 16); lo.y = ls[2] | (ls[3] << 16);
    lo.z = ls[4] | (ls[5] << 16); lo.w = ls[6] | (ls[7] << 16);
}
__device__ __forceinline__ void cvt_pair4(float4 v, uint2& hi, uint2& lo) {
    float f[4] = {v.x, v.y, v.z, v.w};
    unsigned hs[4], ls[4];
    #pragma unroll
    for (int j = 0; j < 4; ++j) {
        __nv_bfloat16 h = __float2bfloat16(f[j]);
        float hf = __bfloat162float(h);
        __nv_bfloat16 l = __float2bfloat16(f[j] - hf);
        hs[j] = (unsigned)__bfloat16_as_ushort(h);
        ls[j] = (unsigned)__bfloat16_as_ushort(l);
    }
    hi.x = hs[0] | (hs[1] << 16); hi.y = hs[2] | (hs[3] << 16);
    lo.x = ls[0] | (ls[1] << 16); lo.y = ls[2] | (ls[3] << 16);
}

// ================= input-projection GEMM on HMMA (unchanged, validated R4) =================
constexpr int GM_THREADS = 256;
constexpr int PITCH = 80;
constexpr int PLANE = 128 * PITCH;
constexpr int SB_BIAS = 0;
constexpr int SB_AH = 1024;
constexpr int SB_AL = SB_AH + PLANE;
constexpr int SB_BH = SB_AL + PLANE;
constexpr int SB_BL = SB_BH + PLANE;
constexpr size_t GM_SMEM = SB_BL + PLANE;

template<int K>
__global__ void __launch_bounds__(GM_THREADS)
gemm_mma(const float* __restrict__ A, const float* __restrict__ W,
         const float* __restrict__ b1, const float* __restrict__ b2,
         float* __restrict__ Cout)
{
    extern __shared__ char sm[];
    const uint32_t sbase = smem_u32(sm);
    float* sbias = (float*)(sm + SB_BIAS);

    const int tid  = threadIdx.x;
    const int lane = tid & 31;
    const int warp = tid >> 5;
    const int wm   = warp >> 2;
    const int wn   = warp & 3;
    const int n0   = blockIdx.x * 128;
    const size_t m0 = (size_t)blockIdx.y * 128;

    if (tid < 128) sbias[tid] = b1[n0 + tid] + b2[n0 + tid];

    const int lrow  = tid >> 1;
    const int lhalf = tid & 1;
    const float* gA = A + (m0 + lrow) * K + lhalf * 16;
    const float* gB = W + (size_t)(n0 + lrow) * K + lhalf * 16;

    float acc[4][4][4] = {};
    float ra[16], rb[16];

    #pragma unroll
    for (int q = 0; q < 4; ++q) {
        *(float4*)(ra + q * 4) = *(const float4*)(gA + q * 4);
        *(float4*)(rb + q * 4) = *(const float4*)(gB + q * 4);
    }

    constexpr int NC = K / 32;
    for (int c = 0; c < NC; ++c) {
        #pragma unroll
        for (int j = 0; j < 2; ++j) {
            uint4 hi, lo;
            uint32_t off = (uint32_t)(lrow * PITCH + lhalf * 32 + j * 16);
            cvt_pair8(ra + j * 8, hi, lo);
            *(uint4*)(sm + SB_AH + off) = hi;
            *(uint4*)(sm + SB_AL + off) = lo;
            cvt_pair8(rb + j * 8, hi, lo);
            *(uint4*)(sm + SB_BH + off) = hi;
            *(uint4*)(sm + SB_BL + off) = lo;
        }
        __syncthreads();

        if (c + 1 < NC) {
            #pragma unroll
            for (int q = 0; q < 4; ++q) {
                *(float4*)(ra + q * 4) = *(const float4*)(gA + (c + 1) * 32 + q * 4);
                *(float4*)(rb + q * 4) = *(const float4*)(gB + (c + 1) * 32 + q * 4);
            }
        }

        #pragma unroll
        for (int kb = 0; kb < 2; ++kb) {
            uint32_t Ah[4][4], Al[4][4], Bh[2][4], Bl[2][4];
            const uint32_t acol = (uint32_t)(kb * 32 + (lane >> 4) * 16);
            #pragma unroll
            for (int mi = 0; mi < 4; ++mi) {
                uint32_t rowoff = (uint32_t)((wm * 64 + mi * 16 + (lane & 15)) * PITCH) + acol;
                ldmx4(Ah[mi], sbase + SB_AH + rowoff);
                ldmx4(Al[mi], sbase + SB_AL + rowoff);
            }
            const uint32_t bcol = (uint32_t)(kb * 32 + ((lane >> 3) & 1) * 16);
            #pragma unroll
            for (int nb = 0; nb < 2; ++nb) {
                uint32_t rowoff = (uint32_t)((wn * 32 + nb * 16 + (lane & 7) + ((lane >> 4) << 3)) * PITCH) + bcol;
                ldmx4(Bh[nb], sbase + SB_BH + rowoff);
                ldmx4(Bl[nb], sbase + SB_BL + rowoff);
            }
            #pragma unroll
            for (int mi = 0; mi < 4; ++mi) {
                #pragma unroll
                for (int ni = 0; ni < 4; ++ni) {
                    const int nb = ni >> 1, h = (ni & 1) * 2;
                    mma16816(acc[mi][ni], Ah[mi], Bh[nb][h], Bh[nb][h + 1]);
                    mma16816(acc[mi][ni], Ah[mi], Bl[nb][h], Bl[nb][h + 1]);
                    mma16816(acc[mi][ni], Al[mi], Bh[nb][h], Bh[nb][h + 1]);
                }
            }
        }
        __syncthreads();
    }

    const int g   = lane >> 2;
    const int tig = lane & 3;
    #pragma unroll
    for (int mi = 0; mi < 4; ++mi) {
        const size_t row = m0 + wm * 64 + mi * 16 + g;
        float* dst0 = Cout + row * G4H + n0;
        float* dst8 = dst0 + (size_t)8 * G4H;
        #pragma unroll
        for (int ni = 0; ni < 4; ++ni) {
            const int col = wn * 32 + ni * 8 + tig * 2;
            const float bb0 = sbias[col], bb1 = sbias[col + 1];
            float2 v0 = {acc[mi][ni][0] + bb0, acc[mi][ni][1] + bb1};
            float2 v1 = {acc[mi][ni][2] + bb0, acc[mi][ni][3] + bb1};
            *(float2*)(dst0 + col) = v0;
            *(float2*)(dst8 + col) = v1;
        }
    }
}

// ================= per-row-group barrier (16 CTAs) =================
__device__ __forceinline__ void group_sync(int grp)
{
    __syncthreads();
    if (threadIdx.x == 0) {
        __threadfence();
        unsigned int gen  = *((volatile unsigned int*)&g_grp_gen[grp][0]);
        unsigned int prev = atomicAdd(&g_grp_count[grp][0], 1u);
        if (prev == GROUP_CTAS - 1) {
            g_grp_count[grp][0] = 0;
            __threadfence();
            atomicAdd(&g_grp_gen[grp][0], 1u);
        } else {
            while (*((volatile unsigned int*)&g_grp_gen[grp][0]) == gen) { }
            __threadfence();
        }
    }
    __syncthreads();
}

__device__ __forceinline__ float sigmoidf_(float x) { return 1.0f / (1.0f + __expf(-x)); }

// ================= persistent LSTM recurrence (mma.sync bf16-pair) =================
// CTA(bi,bu): rows [bi*32,+32), units [bu*16,+16). Sync scope = the 16 CTAs of row-block bi.
constexpr int RPITCH = 528;                       // bytes per 256-bf16 row
constexpr int R_WH_HI = 0;                        // 64*528
constexpr int R_WH_LO = R_WH_HI + 64 * RPITCH;
constexpr int R_AH    = R_WH_LO + 64 * RPITCH;    // 32*528
constexpr int R_AL    = R_AH + 32 * RPITCH;
constexpr int R_GS    = R_AL + 32 * RPITCH;       // 32 x 66 floats
constexpr int R_CS    = R_GS + 32 * 66 * 4;       // 32 x 17 floats
constexpr size_t R_SMEM = (size_t)R_CS + 32 * 17 * 4;   // 112,000 B

__global__ void __launch_bounds__(THREADS_P, 1)
lstm_layer_kernel(const float* __restrict__ Whh,
                  float* __restrict__ y_out,
                  float* __restrict__ out_h,
                  float* __restrict__ out_c)
{
    extern __shared__ char smr[];
    const uint32_t sbase = smem_u32(smr);
    float* Gs = (float*)(smr + R_GS);
    float* Cs = (float*)(smr + R_CS);

    const int tid  = threadIdx.x;
    const int lane = tid & 31;
    const int w    = tid >> 5;          // warp 0..3  (gate w, all 16 units)
    const int bi   = blockIdx.x >> 4;   // row group 0..7
    const int bu   = blockIdx.x & 15;
    const int r0   = bi * 32;
    const int u0   = bu * 16;

    // ---- prologue: convert Whh slice to bf16 pair, pitched ----
    #pragma unroll 4
    for (int it = 0; it < 32; ++it) {
        int idx = tid + it * THREADS_P;      // 0..4095 float4s
        int cc  = idx >> 6;                  // 0..63
        int kf  = idx & 63;
        int g4  = cc >> 4, uu = cc & 15;
        float4 v = *(const float4*)(&Whh[(size_t)(g4 * HID + u0 + uu) * HID + kf * 4]);
        uint2 hi, lo; cvt_pair4(v, hi, lo);
        *(uint2*)(smr + R_WH_HI + cc * RPITCH + kf * 8) = hi;
        *(uint2*)(smr + R_WH_LO + cc * RPITCH + kf * 8) = lo;
    }
    // zero h (this CTA's unit-slice of its rows) and cell state
    for (int q = tid; q < 512; q += THREADS_P) {
        int r = q & 31, uu = q >> 5;
        g_hbf[0][0][(r0 + r) * HID + u0 + uu] = __float2bfloat16(0.0f);
        g_hbf[0][1][(r0 + r) * HID + u0 + uu] = __float2bfloat16(0.0f);
    }
    for (int q = tid; q < 32 * 17; q += THREADS_P) Cs[q] = 0.0f;
    group_sync(bi);

    const int gq  = lane >> 2;          // C-fragment row group
    const int tig = lane & 3;
    const int row_a = tid & 31;         // activation row
    const int ug    = tid >> 5;         // activation unit group: units ug*4..+3

    // xpre base for this thread (advance by G4H per step)
    const float* xp_base = &g_xpre[((size_t)(r0 + row_a) * SEQ) * G4H + u0 + ug * 4];

    // prefetch xpre for t=0
    float xv[4][4];
    #pragma unroll
    for (int g4 = 0; g4 < 4; ++g4) {
        float4 f = *(const float4*)(xp_base + (size_t)g4 * HID);
        xv[g4][0] = f.x; xv[g4][1] = f.y; xv[g4][2] = f.z; xv[g4][3] = f.w;
    }

    int cur = 0;
    for (int t = 0; t < SEQ; ++t) {
        // ---- load h tile (bf16 pair) into SMEM ----
        const __nv_bfloat16* hhi = g_hbf[cur][0];
        const __nv_bfloat16* hlo = g_hbf[cur][1];
        #pragma unroll
        for (int it = 0; it < 8; ++it) {
            int idx = tid + it * THREADS_P;   // 0..1023 chunks of 16B
            int row = idx >> 5, ch = idx & 31;
            uint4 v = __ldcg((const uint4*)(hhi + (r0 + row) * HID) + ch);
            *(uint4*)(smr + R_AH + row * RPITCH + ch * 16) = v;
            v = __ldcg((const uint4*)(hlo + (r0 + row) * HID) + ch);
            *(uint4*)(smr + R_AL + row * RPITCH + ch * 16) = v;
        }
        __syncthreads();

        // ---- recurrent GEMM: 32(m) x 16(n per warp), K=256, bf16-pair ----
        float acc[2][2][4] = {};
        #pragma unroll 4
        for (int kb = 0; kb < 16; ++kb) {
            uint32_t Ahf[2][4], Alf[2][4], Bhf[4], Blf[4];
            const uint32_t acol = (uint32_t)(kb * 32 + (lane >> 4) * 16);
            #pragma unroll
            for (int mi = 0; mi < 2; ++mi) {
                uint32_t ro = (uint32_t)((mi * 16 + (lane & 15)) * RPITCH) + acol;
                ldmx4(Ahf[mi], sbase + R_AH + ro);
                ldmx4(Alf[mi], sbase + R_AL + ro);
            }
            const uint32_t brow = (uint32_t)(w * 16 + (lane & 7) + ((lane >> 4) << 3));
            const uint32_t bcol = (uint32_t)(kb * 32 + ((lane >> 3) & 1) * 16);
            ldmx4(Bhf, sbase + R_WH_HI + brow * RPITCH + bcol);
            ldmx4(Blf, sbase + R_WH_LO + brow * RPITCH + bcol);
            #pragma unroll
            for (int mi = 0; mi < 2; ++mi) {
                #pragma unroll
                for (int ni = 0; ni < 2; ++ni) {
                    const int h2 = ni * 2;
                    mma16816(acc[mi][ni], Ahf[mi], Bhf[h2], Bhf[h2 + 1]);
                    mma16816(acc[mi][ni], Ahf[mi], Blf[h2], Blf[h2 + 1]);
                    mma16816(acc[mi][ni], Alf[mi], Bhf[h2], Bhf[h2 + 1]);
                }
            }
        }

        // ---- store C fragments to Gs (pitch 66 floats) ----
        #pragma unroll
        for (int mi = 0; mi < 2; ++mi) {
            #pragma unroll
            for (int ni = 0; ni < 2; ++ni) {
                const int col = w * 16 + ni * 8 + tig * 2;
                float2 v0 = {acc[mi][ni][0], acc[mi][ni][1]};
                float2 v1 = {acc[mi][ni][2], acc[mi][ni][3]};
                *(float2*)(&Gs[(mi * 16 + gq) * 66 + col])     = v0;
                *(float2*)(&Gs[(mi * 16 + gq + 8) * 66 + col]) = v1;
            }
        }
        __syncthreads();

        // ---- activations: thread owns (row_a, units ug*4..+3) ----
        __nv_bfloat16* dhi = g_hbf[cur ^ 1][0];
        __nv_bfloat16* dlo = g_hbf[cur ^ 1][1];
        unsigned hh[4], hl[4];
        float4 yv, cv;
        float* ys = (float*)&yv;
        float* cs4 = (float*)&cv;
        #pragma unroll
        for (int j = 0; j < 4; ++j) {
            int uu = ug * 4 + j;
            float gi = Gs[row_a * 66 +      uu] + xv[0][j];
            float gf = Gs[row_a * 66 + 16 + uu] + xv[1][j];
            float gg = Gs[row_a * 66 + 32 + uu] + xv[2][j];
            float go = Gs[row_a * 66 + 48 + uu] + xv[3][j];
            float ig = sigmoidf_(gi);
            float fg = sigmoidf_(gf);
            float og = sigmoidf_(go);
            float gc = tanhf(gg);
            float c  = fg * Cs[row_a * 17 + uu] + ig * gc;
            float h  = og * tanhf(c);
            Cs[row_a * 17 + uu] = c;
            __nv_bfloat16 hb = __float2bfloat16(h);
            float hf = __bfloat162float(hb);
            __nv_bfloat16 lb = __float2bfloat16(h - hf);
            hh[j] = (unsigned)__bfloat16_as_ushort(hb);
            hl[j] = (unsigned)__bfloat16_as_ushort(lb);
            ys[j] = h;
            cs4[j] = c;
        }
        {
            const int uoff = (r0 + row_a) * HID + u0 + ug * 4;
            uint2 ph = {hh[0] | (hh[1] << 16), hh[2] | (hh[3] << 16)};
            uint2 pl = {hl[0] | (hl[1] << 16), hl[2] | (hl[3] << 16)};
            *(uint2*)(dhi + uoff) = ph;
            *(uint2*)(dlo + uoff) = pl;
            *(float4*)(&y_out[((size_t)(r0 + row_a) * SEQ + t) * HID + u0 + ug * 4]) = yv;
            if (out_h != nullptr && t == SEQ - 1) {
                *(float4*)(&out_h[uoff]) = yv;
                *(float4*)(&out_c[uoff]) = cv;
            }
        }

        // ---- prefetch next step's xpre BEFORE the barrier (hide DRAM latency) ----
        if (t + 1 < SEQ) {
            const float* xp = xp_base + (size_t)(t + 1) * G4H;
            #pragma unroll
            for (int g4 = 0; g4 < 4; ++g4) {
                float4 f = *(const float4*)(xp + (size_t)g4 * HID);
                xv[g4][0] = f.x; xv[g4][1] = f.y; xv[g4][2] = f.z; xv[g4][3] = f.w;
            }
        }

        group_sync(bi);   // only the 16 CTAs of this row block
        cur ^= 1;
    }
}

// ================= launch =================
extern "C" void kernel_launch(void* const* d_in, const int* in_sizes, int n_in,
                              void* d_out, int out_size)
{
    const float* x    = (const float*)d_in[0];
    const float* Wih0 = (const float*)d_in[1];
    const float* Whh0 = (const float*)d_in[2];
    const float* bih0 = (const float*)d_in[3];
    const float* bhh0 = (const float*)d_in[4];
    const float* Wih1 = (const float*)d_in[5];
    const float* Whh1 = (const float*)d_in[6];
    const float* bih1 = (const float*)d_in[7];
    const float* bhh1 = (const float*)d_in[8];
    float* out = (float*)d_out;

    float* y0_ptr = nullptr;
    float* xpre_ptr = nullptr;
    cudaGetSymbolAddress((void**)&y0_ptr, g_y0);
    cudaGetSymbolAddress((void**)&xpre_ptr, g_xpre);

    cudaFuncSetAttribute(lstm_layer_kernel,
                         cudaFuncAttributeMaxDynamicSharedMemorySize, (int)R_SMEM);
    cudaFuncSetAttribute(gemm_mma<INP>,
                         cudaFuncAttributeMaxDynamicSharedMemorySize, (int)GM_SMEM);
    cudaFuncSetAttribute(gemm_mma<HID>,
                         cudaFuncAttributeMaxDynamicSharedMemorySize, (int)GM_SMEM);

    dim3 tgrid(G4H / 128, (BATCH * SEQ) / 128);   // (8, 1024)

    // Layer 0
    gemm_mma<INP><<<tgrid, GM_THREADS, GM_SMEM>>>(x, Wih0, bih0, bhh0, xpre_ptr);
    lstm_layer_kernel<<<GRID_P, THREADS_P, R_SMEM>>>(Whh0, y0_ptr, nullptr, nullptr);

    // Layer 1
    gemm_mma<HID><<<tgrid, GM_THREADS, GM_SMEM>>>(y0_ptr, Wih1, bih1, bhh1, xpre_ptr);
    float* out_h = out + (size_t)BATCH * SEQ * HID;
    float* out_c = out_h + (size_t)BATCH * HID;
    lstm_layer_kernel<<<GRID_P, THREADS_P, R_SMEM>>>(Whh1, out, out_h, out_c);
}

// round 12
// speedup vs baseline: 2.1815x; 1.0130x over previous
#include <cuda_runtime.h>
#include <cuda_bf16.h>
#include <cstdint>
#include <cstddef>

// Problem constants
constexpr int BATCH = 256;
constexpr int SEQ   = 512;
constexpr int INP   = 128;
constexpr int HID   = 256;
constexpr int G4H   = 1024;   // 4*HID

// Persistent recurrent kernel config
constexpr int GRID_P    = 128;   // 8 row-blocks x 16 unit-blocks, co-resident
constexpr int THREADS_P = 128;
constexpr int GROUP_CTAS = 16;   // CTAs per row-block sync group

// ---------------- scratch ----------------
__device__ float g_xpre0[(size_t)BATCH * SEQ * G4H];       // 512 MB: layer-0 pre-acts
__device__ float g_xpre1[(size_t)BATCH * SEQ * G4H];       // 512 MB: layer-1 pre-acts
__device__ __nv_bfloat16 g_hbf[2][2][BATCH * HID];         // [buf][hi/lo][B*H]
// per-row-group barrier state, 256B padding between groups
__device__ unsigned int g_grp_count[8][64];
__device__ unsigned int g_grp_gen[8][64];

__device__ __forceinline__ uint32_t smem_u32(const void* p) {
    uint32_t a;
    asm("{ .reg .u64 t; cvta.to.shared.u64 t, %1; cvt.u32.u64 %0, t; }" : "=r"(a) : "l"(p));
    return a;
}

// ================= mma.sync helpers (baseline PTX, sm_80+) =================
__device__ __forceinline__ void ldmx4(uint32_t* r, uint32_t addr) {
    asm volatile("ldmatrix.sync.aligned.m8n8.x4.shared.b16 {%0,%1,%2,%3}, [%4];"
                 : "=r"(r[0]), "=r"(r[1]), "=r"(r[2]), "=r"(r[3]) : "r"(addr));
}
__device__ __forceinline__ void mma16816(float* d, const uint32_t* a,
                                         uint32_t b0, uint32_t b1) {
    asm volatile(
        "mma.sync.aligned.m16n8k16.row.col.f32.bf16.bf16.f32 "
        "{%0,%1,%2,%3}, {%4,%5,%6,%7}, {%8,%9}, {%0,%1,%2,%3};"
        : "+f"(d[0]), "+f"(d[1]), "+f"(d[2]), "+f"(d[3])
        : "r"(a[0]), "r"(a[1]), "r"(a[2]), "r"(a[3]), "r"(b0), "r"(b1));
}

__device__ __forceinline__ void cvt_pair8(const float* v, uint4& hi, uint4& lo) {
    unsigned hs[8], ls[8];
    #pragma unroll
    for (int j = 0; j < 8; ++j) {
        __nv_bfloat16 h = __float2bfloat16(v[j]);
        float hf = __bfloat162float(h);
        __nv_bfloat16 l = __float2bfloat16(v[j] - hf);
        hs[j] = (unsigned)__bfloat16_as_ushort(h);
        ls[j] = (unsigned)__bfloat16_as_ushort(l);
    }
    hi.x = hs[0] | (hs[1] << 16); hi.y = hs[2] | (hs[3] << 16);
    hi.z = hs[4] | (hs[5] << 16); hi.w = hs[6] | (hs[7] << 16);
    lo.x = ls[0] | (ls[1] << 16); lo.y = ls[2] | (ls[3] << 16);
    lo.z = ls[4] | (ls[5] << 16); lo.w = ls[6] | (ls[7] << 16);
}
__device__ __forceinline__ void cvt_pair4(float4 v, uint2& hi, uint2& lo) {
    float f[4] = {v.x, v.y, v.z, v.w};
    unsigned hs[4], ls[4];
    #pragma unroll
    for (int j = 0; j < 4; ++j) {
        __nv_bfloat16 h = __float2bfloat16(f[j]);
        float hf = __bfloat162float(h);
        __nv_bfloat16 l = __float2bfloat16(f[j] - hf);
        hs[j] = (unsigned)__bfloat16_as_ushort(h);
        ls[j] = (unsigned)__bfloat16_as_ushort(l);
    }
    hi.x = hs[0] | (hs[1] << 16); hi.y = hs[2] | (hs[3] << 16);
    lo.x = ls[0] | (ls[1] << 16); lo.y = ls[2] | (ls[3] << 16);
}

// ================= input-projection GEMM on HMMA (layer 0 only) =================
constexpr int GM_THREADS = 256;
constexpr int PITCH = 80;
constexpr int PLANE = 128 * PITCH;
constexpr int SB_BIAS = 0;
constexpr int SB_AH = 1024;
constexpr int SB_AL = SB_AH + PLANE;
constexpr int SB_BH = SB_AL + PLANE;
constexpr int SB_BL = SB_BH + PLANE;
constexpr size_t GM_SMEM = SB_BL + PLANE;

template<int K>
__global__ void __launch_bounds__(GM_THREADS)
gemm_mma(const float* __restrict__ A, const float* __restrict__ W,
         const float* __restrict__ b1, const float* __restrict__ b2,
         float* __restrict__ Cout)
{
    extern __shared__ char sm[];
    const uint32_t sbase = smem_u32(sm);
    float* sbias = (float*)(sm + SB_BIAS);

    const int tid  = threadIdx.x;
    const int lane = tid & 31;
    const int warp = tid >> 5;
    const int wm   = warp >> 2;
    const int wn   = warp & 3;
    const int n0   = blockIdx.x * 128;
    const size_t m0 = (size_t)blockIdx.y * 128;

    if (tid < 128) sbias[tid] = b1[n0 + tid] + b2[n0 + tid];

    const int lrow  = tid >> 1;
    const int lhalf = tid & 1;
    const float* gA = A + (m0 + lrow) * K + lhalf * 16;
    const float* gB = W + (size_t)(n0 + lrow) * K + lhalf * 16;

    float acc[4][4][4] = {};
    float ra[16], rb[16];

    #pragma unroll
    for (int q = 0; q < 4; ++q) {
        *(float4*)(ra + q * 4) = *(const float4*)(gA + q * 4);
        *(float4*)(rb + q * 4) = *(const float4*)(gB + q * 4);
    }

    constexpr int NC = K / 32;
    for (int c = 0; c < NC; ++c) {
        #pragma unroll
        for (int j = 0; j < 2; ++j) {
            uint4 hi, lo;
            uint32_t off = (uint32_t)(lrow * PITCH + lhalf * 32 + j * 16);
            cvt_pair8(ra + j * 8, hi, lo);
            *(uint4*)(sm + SB_AH + off) = hi;
            *(uint4*)(sm + SB_AL + off) = lo;
            cvt_pair8(rb + j * 8, hi, lo);
            *(uint4*)(sm + SB_BH + off) = hi;
            *(uint4*)(sm + SB_BL + off) = lo;
        }
        __syncthreads();

        if (c + 1 < NC) {
            #pragma unroll
            for (int q = 0; q < 4; ++q) {
                *(float4*)(ra + q * 4) = *(const float4*)(gA + (c + 1) * 32 + q * 4);
                *(float4*)(rb + q * 4) = *(const float4*)(gB + (c + 1) * 32 + q * 4);
            }
        }

        #pragma unroll
        for (int kb = 0; kb < 2; ++kb) {
            uint32_t Ah[4][4], Al[4][4], Bh[2][4], Bl[2][4];
            const uint32_t acol = (uint32_t)(kb * 32 + (lane >> 4) * 16);
            #pragma unroll
            for (int mi = 0; mi < 4; ++mi) {
                uint32_t rowoff = (uint32_t)((wm * 64 + mi * 16 + (lane & 15)) * PITCH) + acol;
                ldmx4(Ah[mi], sbase + SB_AH + rowoff);
                ldmx4(Al[mi], sbase + SB_AL + rowoff);
            }
            const uint32_t bcol = (uint32_t)(kb * 32 + ((lane >> 3) & 1) * 16);
            #pragma unroll
            for (int nb = 0; nb < 2; ++nb) {
                uint32_t rowoff = (uint32_t)((wn * 32 + nb * 16 + (lane & 7) + ((lane >> 4) << 3)) * PITCH) + bcol;
                ldmx4(Bh[nb], sbase + SB_BH + rowoff);
                ldmx4(Bl[nb], sbase + SB_BL + rowoff);
            }
            #pragma unroll
            for (int mi = 0; mi < 4; ++mi) {
                #pragma unroll
                for (int ni = 0; ni < 4; ++ni) {
                    const int nb = ni >> 1, h = (ni & 1) * 2;
                    mma16816(acc[mi][ni], Ah[mi], Bh[nb][h], Bh[nb][h + 1]);
                    mma16816(acc[mi][ni], Ah[mi], Bl[nb][h], Bl[nb][h + 1]);
                    mma16816(acc[mi][ni], Al[mi], Bh[nb][h], Bh[nb][h + 1]);
                }
            }
        }
        __syncthreads();
    }

    const int g   = lane >> 2;
    const int tig = lane & 3;
    #pragma unroll
    for (int mi = 0; mi < 4; ++mi) {
        const size_t row = m0 + wm * 64 + mi * 16 + g;
        float* dst0 = Cout + row * G4H + n0;
        float* dst8 = dst0 + (size_t)8 * G4H;
        #pragma unroll
        for (int ni = 0; ni < 4; ++ni) {
            const int col = wn * 32 + ni * 8 + tig * 2;
            const float bb0 = sbias[col], bb1 = sbias[col + 1];
            float2 v0 = {acc[mi][ni][0] + bb0, acc[mi][ni][1] + bb1};
            float2 v1 = {acc[mi][ni][2] + bb0, acc[mi][ni][3] + bb1};
            *(float2*)(dst0 + col) = v0;
            *(float2*)(dst8 + col) = v1;
        }
    }
}

// ================= per-row-group barrier (16 CTAs) =================
__device__ __forceinline__ void group_sync(int grp)
{
    __syncthreads();
    if (threadIdx.x == 0) {
        __threadfence();
        unsigned int gen  = *((volatile unsigned int*)&g_grp_gen[grp][0]);
        unsigned int prev = atomicAdd(&g_grp_count[grp][0], 1u);
        if (prev == GROUP_CTAS - 1) {
            g_grp_count[grp][0] = 0;
            __threadfence();
            atomicAdd(&g_grp_gen[grp][0], 1u);
        } else {
            while (*((volatile unsigned int*)&g_grp_gen[grp][0]) == gen) { }
            __threadfence();
        }
    }
    __syncthreads();
}

__device__ __forceinline__ float sigmoidf_(float x) { return 1.0f / (1.0f + __expf(-x)); }

// ================= persistent LSTM recurrence; FUSED adds next-layer projection ========
// CTA(bi,bu): rows [bi*32,+32), units [bu*16,+16).
// SMEM planes (bf16 pair, pitch 528 B): Whh slice, Wih_next slice, h tile.
constexpr int RPITCH  = 528;
constexpr int R_WH_HI = 0;                          // 64 rows
constexpr int R_WH_LO = R_WH_HI + 64 * RPITCH;      // 33792
constexpr int R_WN_HI = R_WH_LO + 64 * RPITCH;      // 67584
constexpr int R_WN_LO = R_WN_HI + 64 * RPITCH;      // 101376
constexpr int R_AH    = R_WN_LO + 64 * RPITCH;      // 135168 (32 rows)
constexpr int R_AL    = R_AH + 32 * RPITCH;         // 152064
constexpr int R_GS    = R_AL + 32 * RPITCH;         // 168960 (32 x 66 floats)
constexpr int R_CS    = R_GS + 32 * 66 * 4;         // 177408 (32 x 17 floats)
constexpr int R_BN    = R_CS + 32 * 17 * 4;         // 179584 (64 floats next-layer bias)
constexpr size_t R_SMEM = (size_t)R_BN + 64 * 4;    // 179840 B

// Load this CTA's h tile (bf16 pair) from the given buffer into the As planes.
__device__ __forceinline__ void load_h_tile(char* smr, const __nv_bfloat16* hhi,
                                            const __nv_bfloat16* hlo, int r0, int tid)
{
    #pragma unroll
    for (int it = 0; it < 8; ++it) {
        int idx = tid + it * THREADS_P;   // 0..1023 chunks of 16B
        int row = idx >> 5, ch = idx & 31;
        uint4 v = __ldcg((const uint4*)(hhi + (r0 + row) * HID) + ch);
        *(uint4*)(smr + R_AH + row * RPITCH + ch * 16) = v;
        v = __ldcg((const uint4*)(hlo + (r0 + row) * HID) + ch);
        *(uint4*)(smr + R_AL + row * RPITCH + ch * 16) = v;
    }
}

// Projection MMAs over the current As planes against the Wih_next planes.
__device__ __forceinline__ void proj_mma(const uint32_t sbase, int lane, int w,
                                         float acc2[2][2][4])
{
    #pragma unroll 4
    for (int kb = 0; kb < 16; ++kb) {
        uint32_t Ahf[2][4], Alf[2][4], Bnh[4], Bnl[4];
        const uint32_t acol = (uint32_t)(kb * 32 + (lane >> 4) * 16);
        #pragma unroll
        for (int mi = 0; mi < 2; ++mi) {
            uint32_t ro = (uint32_t)((mi * 16 + (lane & 15)) * RPITCH) + acol;
            ldmx4(Ahf[mi], sbase + R_AH + ro);
            ldmx4(Alf[mi], sbase + R_AL + ro);
        }
        const uint32_t brow = (uint32_t)(w * 16 + (lane & 7) + ((lane >> 4) << 3));
        const uint32_t bcol = (uint32_t)(kb * 32 + ((lane >> 3) & 1) * 16);
        ldmx4(Bnh, sbase + R_WN_HI + brow * RPITCH + bcol);
        ldmx4(Bnl, sbase + R_WN_LO + brow * RPITCH + bcol);
        #pragma unroll
        for (int mi = 0; mi < 2; ++mi)
            #pragma unroll
            for (int ni = 0; ni < 2; ++ni) {
                const int h2 = ni * 2;
                mma16816(acc2[mi][ni], Ahf[mi], Bnh[h2], Bnh[h2 + 1]);
                mma16816(acc2[mi][ni], Ahf[mi], Bnl[h2], Bnl[h2 + 1]);
                mma16816(acc2[mi][ni], Alf[mi], Bnh[h2], Bnh[h2 + 1]);
            }
    }
}

// Store projection results (+bias) to xpre_out[:, t_store].
__device__ __forceinline__ void proj_store(float* __restrict__ xpre_out, const float* sbn,
                                           float acc2[2][2][4], int t_store,
                                           int r0, int u0, int w, int gq, int tig)
{
    #pragma unroll
    for (int mi = 0; mi < 2; ++mi) {
        const int row = r0 + mi * 16 + gq;
        float* d0 = xpre_out + ((size_t)row * SEQ + t_store) * G4H + w * HID + u0;
        float* d8 = xpre_out + ((size_t)(row + 8) * SEQ + t_store) * G4H + w * HID + u0;
        #pragma unroll
        for (int ni = 0; ni < 2; ++ni) {
            const int uu = ni * 8 + tig * 2;
            const float b0 = sbn[w * 16 + uu], b1v = sbn[w * 16 + uu + 1];
            float2 v0 = {acc2[mi][ni][0] + b0, acc2[mi][ni][1] + b1v};
            float2 v1 = {acc2[mi][ni][2] + b0, acc2[mi][ni][3] + b1v};
            *(float2*)(d0 + uu) = v0;
            *(float2*)(d8 + uu) = v1;
        }
    }
}

template<bool FUSED>
__global__ void __launch_bounds__(THREADS_P, 1)
lstm_layer_kernel(const float* __restrict__ Whh,
                  const float* __restrict__ xpre_in,
                  const float* __restrict__ Wih_next,
                  const float* __restrict__ bn1,
                  const float* __restrict__ bn2,
                  float* __restrict__ xpre_out,
                  float* __restrict__ y_out,
                  float* __restrict__ out_h,
                  float* __restrict__ out_c)
{
    extern __shared__ char smr[];
    const uint32_t sbase = smem_u32(smr);
    float* Gs  = (float*)(smr + R_GS);
    float* Cs  = (float*)(smr + R_CS);
    float* sbn = (float*)(smr + R_BN);

    const int tid  = threadIdx.x;
    const int lane = tid & 31;
    const int w    = tid >> 5;          // warp 0..3 (gate w)
    const int bi   = blockIdx.x >> 4;   // row group 0..7
    const int bu   = blockIdx.x & 15;
    const int r0   = bi * 32;
    const int u0   = bu * 16;

    // ---- prologue: convert Whh slice (and Wih_next slice) to bf16-pair planes ----
    #pragma unroll 4
    for (int it = 0; it < 32; ++it) {
        int idx = tid + it * THREADS_P;      // 0..4095 float4s
        int cc  = idx >> 6;                  // 0..63
        int kf  = idx & 63;
        int g4  = cc >> 4, uu = cc & 15;
        float4 v = *(const float4*)(&Whh[(size_t)(g4 * HID + u0 + uu) * HID + kf * 4]);
        uint2 hi, lo; cvt_pair4(v, hi, lo);
        *(uint2*)(smr + R_WH_HI + cc * RPITCH + kf * 8) = hi;
        *(uint2*)(smr + R_WH_LO + cc * RPITCH + kf * 8) = lo;
    }
    if (FUSED) {
        #pragma unroll 4
        for (int it = 0; it < 32; ++it) {
            int idx = tid + it * THREADS_P;
            int cc  = idx >> 6;
            int kf  = idx & 63;
            int g4  = cc >> 4, uu = cc & 15;
            float4 v = *(const float4*)(&Wih_next[(size_t)(g4 * HID + u0 + uu) * HID + kf * 4]);
            uint2 hi, lo; cvt_pair4(v, hi, lo);
            *(uint2*)(smr + R_WN_HI + cc * RPITCH + kf * 8) = hi;
            *(uint2*)(smr + R_WN_LO + cc * RPITCH + kf * 8) = lo;
        }
        if (tid < 64) {
            int g4 = tid >> 4, uu = tid & 15;
            sbn[tid] = bn1[g4 * HID + u0 + uu] + bn2[g4 * HID + u0 + uu];
        }
    }
    for (int q = tid; q < 512; q += THREADS_P) {
        int r = q & 31, uu = q >> 5;
        g_hbf[0][0][(r0 + r) * HID + u0 + uu] = __float2bfloat16(0.0f);
        g_hbf[0][1][(r0 + r) * HID + u0 + uu] = __float2bfloat16(0.0f);
    }
    for (int q = tid; q < 32 * 17; q += THREADS_P) Cs[q] = 0.0f;
    group_sync(bi);

    const int gq  = lane >> 2;          // C-fragment row group
    const int tig = lane & 3;
    const int row_a = tid & 31;         // activation row
    const int ug    = tid >> 5;         // activation unit group

    const float* xp_base = xpre_in + ((size_t)(r0 + row_a) * SEQ) * G4H + u0 + ug * 4;

    // prefetch xpre for t=0
    float xv[4][4];
    #pragma unroll
    for (int g4 = 0; g4 < 4; ++g4) {
        float4 f = *(const float4*)(xp_base + (size_t)g4 * HID);
        xv[g4][0] = f.x; xv[g4][1] = f.y; xv[g4][2] = f.z; xv[g4][3] = f.w;
    }

    int cur = 0;
    for (int t = 0; t < SEQ; ++t) {
        // ---- load h tile (h_{t-1}, bf16 pair) into SMEM ----
        load_h_tile(smr, g_hbf[cur][0], g_hbf[cur][1], r0, tid);
        __syncthreads();

        // ---- gate MMAs: h_{t-1} @ Whh ----
        float acc[2][2][4] = {};
        #pragma unroll 4
        for (int kb = 0; kb < 16; ++kb) {
            uint32_t Ahf[2][4], Alf[2][4], Bhf[4], Blf[4];
            const uint32_t acol = (uint32_t)(kb * 32 + (lane >> 4) * 16);
            #pragma unroll
            for (int mi = 0; mi < 2; ++mi) {
                uint32_t ro = (uint32_t)((mi * 16 + (lane & 15)) * RPITCH) + acol;
                ldmx4(Ahf[mi], sbase + R_AH + ro);
                ldmx4(Alf[mi], sbase + R_AL + ro);
            }
            const uint32_t brow = (uint32_t)(w * 16 + (lane & 7) + ((lane >> 4) << 3));
            const uint32_t bcol = (uint32_t)(kb * 32 + ((lane >> 3) & 1) * 16);
            ldmx4(Bhf, sbase + R_WH_HI + brow * RPITCH + bcol);
            ldmx4(Blf, sbase + R_WH_LO + brow * RPITCH + bcol);
            #pragma unroll
            for (int mi = 0; mi < 2; ++mi)
                #pragma unroll
                for (int ni = 0; ni < 2; ++ni) {
                    const int h2 = ni * 2;
                    mma16816(acc[mi][ni], Ahf[mi], Bhf[h2], Bhf[h2 + 1]);
                    mma16816(acc[mi][ni], Ahf[mi], Blf[h2], Blf[h2 + 1]);
                    mma16816(acc[mi][ni], Alf[mi], Bhf[h2], Bhf[h2 + 1]);
                }
        }

        // ---- fused projection MMAs: h_{t-1} @ Wih_next (store for t>0) ----
        if (FUSED) {
            float acc2[2][2][4] = {};
            proj_mma(sbase, lane, w, acc2);
            if (t > 0)
                proj_store(xpre_out, sbn, acc2, t - 1, r0, u0, w, gq, tig);
        }

        // ---- exchange gate fragments through Gs ----
        #pragma unroll
        for (int mi = 0; mi < 2; ++mi)
            #pragma unroll
            for (int ni = 0; ni < 2; ++ni) {
                const int col = w * 16 + ni * 8 + tig * 2;
                float2 v0 = {acc[mi][ni][0], acc[mi][ni][1]};
                float2 v1 = {acc[mi][ni][2], acc[mi][ni][3]};
                *(float2*)(&Gs[(mi * 16 + gq) * 66 + col])     = v0;
                *(float2*)(&Gs[(mi * 16 + gq + 8) * 66 + col]) = v1;
            }
        __syncthreads();

        // ---- activations: thread owns (row_a, units ug*4..+3) ----
        __nv_bfloat16* dhi = g_hbf[cur ^ 1][0];
        __nv_bfloat16* dlo = g_hbf[cur ^ 1][1];
        unsigned hh[4], hl[4];
        float4 yv, cv;
        float* ys  = (float*)&yv;
        float* cs4 = (float*)&cv;
        #pragma unroll
        for (int j = 0; j < 4; ++j) {
            int uu = ug * 4 + j;
            float gi = Gs[row_a * 66 +      uu] + xv[0][j];
            float gf = Gs[row_a * 66 + 16 + uu] + xv[1][j];
            float gg = Gs[row_a * 66 + 32 + uu] + xv[2][j];
            float go = Gs[row_a * 66 + 48 + uu] + xv[3][j];
            float ig = sigmoidf_(gi);
            float fg = sigmoidf_(gf);
            float og = sigmoidf_(go);
            float gc = tanhf(gg);
            float c  = fg * Cs[row_a * 17 + uu] + ig * gc;
            float h  = og * tanhf(c);
            Cs[row_a * 17 + uu] = c;
            __nv_bfloat16 hb = __float2bfloat16(h);
            float hf = __bfloat162float(hb);
            __nv_bfloat16 lb = __float2bfloat16(h - hf);
            hh[j] = (unsigned)__bfloat16_as_ushort(hb);
            hl[j] = (unsigned)__bfloat16_as_ushort(lb);
            ys[j] = h;
            cs4[j] = c;
        }
        {
            const int uoff = (r0 + row_a) * HID + u0 + ug * 4;
            uint2 ph = {hh[0] | (hh[1] << 16), hh[2] | (hh[3] << 16)};
            uint2 pl = {hl[0] | (hl[1] << 16), hl[2] | (hl[3] << 16)};
            *(uint2*)(dhi + uoff) = ph;
            *(uint2*)(dlo + uoff) = pl;
            if (y_out != nullptr)
                *(float4*)(&y_out[((size_t)(r0 + row_a) * SEQ + t) * HID + u0 + ug * 4]) = yv;
            if (out_h != nullptr && t == SEQ - 1) {
                *(float4*)(&out_h[uoff]) = yv;
                *(float4*)(&out_c[uoff]) = cv;
            }
        }

        // ---- prefetch next step's xpre before the barrier ----
        if (t + 1 < SEQ) {
            const float* xp = xp_base + (size_t)(t + 1) * G4H;
            #pragma unroll
            for (int g4 = 0; g4 < 4; ++g4) {
                float4 f = *(const float4*)(xp + (size_t)g4 * HID);
                xv[g4][0] = f.x; xv[g4][1] = f.y; xv[g4][2] = f.z; xv[g4][3] = f.w;
            }
        }

        group_sync(bi);
        cur ^= 1;
    }

    // ---- epilogue (FUSED): project h_{SEQ-1} -> xpre_out[:, SEQ-1] ----
    if (FUSED) {
        load_h_tile(smr, g_hbf[cur][0], g_hbf[cur][1], r0, tid);
        __syncthreads();
        float acc2[2][2][4] = {};
        proj_mma(sbase, lane, w, acc2);
        proj_store(xpre_out, sbn, acc2, SEQ - 1, r0, u0, w, gq, tig);
    }
}

// ================= launch =================
extern "C" void kernel_launch(void* const* d_in, const int* in_sizes, int n_in,
                              void* d_out, int out_size)
{
    const float* x    = (const float*)d_in[0];
    const float* Wih0 = (const float*)d_in[1];
    const float* Whh0 = (const float*)d_in[2];
    const float* bih0 = (const float*)d_in[3];
    const float* bhh0 = (const float*)d_in[4];
    const float* Wih1 = (const float*)d_in[5];
    const float* Whh1 = (const float*)d_in[6];
    const float* bih1 = (const float*)d_in[7];
    const float* bhh1 = (const float*)d_in[8];
    float* out = (float*)d_out;

    float* xpre0 = nullptr;
    float* xpre1 = nullptr;
    cudaGetSymbolAddress((void**)&xpre0, g_xpre0);
    cudaGetSymbolAddress((void**)&xpre1, g_xpre1);

    cudaFuncSetAttribute(lstm_layer_kernel<true>,
                         cudaFuncAttributeMaxDynamicSharedMemorySize, (int)R_SMEM);
    cudaFuncSetAttribute(lstm_layer_kernel<false>,
                         cudaFuncAttributeMaxDynamicSharedMemorySize, (int)R_SMEM);
    cudaFuncSetAttribute(gemm_mma<INP>,
                         cudaFuncAttributeMaxDynamicSharedMemorySize, (int)GM_SMEM);

    dim3 tgrid(G4H / 128, (BATCH * SEQ) / 128);   // (8, 1024)

    // Layer 0: input projection (x @ Wih0^T), then recurrence with FUSED layer-1 projection
    gemm_mma<INP><<<tgrid, GM_THREADS, GM_SMEM>>>(x, Wih0, bih0, bhh0, xpre0);
    lstm_layer_kernel<true><<<GRID_P, THREADS_P, R_SMEM>>>(
        Whh0, xpre0, Wih1, bih1, bhh1, xpre1, nullptr, nullptr, nullptr);

    // Layer 1: recurrence only (xpre1 already produced by layer 0's fused projection)
    float* out_h = out + (size_t)BATCH * SEQ * HID;
    float* out_c = out_h + (size_t)BATCH * HID;
    lstm_layer_kernel<false><<<GRID_P, THREADS_P, R_SMEM>>>(
        Whh1, xpre1, nullptr, nullptr, nullptr, nullptr, out, out_h, out_c);
}

// round 13
// speedup vs baseline: 2.3349x; 1.0703x over previous
#include <cuda_runtime.h>
#include <cuda_bf16.h>
#include <cstdint>
#include <cstddef>

// Problem constants
constexpr int BATCH = 256;
constexpr int SEQ   = 512;
constexpr int INP   = 128;
constexpr int HID   = 256;
constexpr int G4H   = 1024;   // 4*HID

// Persistent recurrent kernel config
constexpr int GRID_P    = 128;   // 8 row-blocks x 16 unit-blocks, co-resident
constexpr int THREADS_R = 256;   // 8 warps: 4 gate + 4 proj/splitK
constexpr int GROUP_CTAS = 16;   // CTAs per row-block sync group

// ---------------- scratch ----------------
__device__ float g_xpre0[(size_t)BATCH * SEQ * G4H];       // 512 MB
__device__ float g_xpre1[(size_t)BATCH * SEQ * G4H];       // 512 MB
__device__ __nv_bfloat16 g_hbf[2][2][BATCH * HID];         // [buf][hi/lo][B*H]
__device__ unsigned int g_grp_count[8][64];
__device__ unsigned int g_grp_gen[8][64];

__device__ __forceinline__ uint32_t smem_u32(const void* p) {
    uint32_t a;
    asm("{ .reg .u64 t; cvta.to.shared.u64 t, %1; cvt.u32.u64 %0, t; }" : "=r"(a) : "l"(p));
    return a;
}

// ================= mma.sync helpers =================
__device__ __forceinline__ void ldmx4(uint32_t* r, uint32_t addr) {
    asm volatile("ldmatrix.sync.aligned.m8n8.x4.shared.b16 {%0,%1,%2,%3}, [%4];"
                 : "=r"(r[0]), "=r"(r[1]), "=r"(r[2]), "=r"(r[3]) : "r"(addr));
}
__device__ __forceinline__ void mma16816(float* d, const uint32_t* a,
                                         uint32_t b0, uint32_t b1) {
    asm volatile(
        "mma.sync.aligned.m16n8k16.row.col.f32.bf16.bf16.f32 "
        "{%0,%1,%2,%3}, {%4,%5,%6,%7}, {%8,%9}, {%0,%1,%2,%3};"
        : "+f"(d[0]), "+f"(d[1]), "+f"(d[2]), "+f"(d[3])
        : "r"(a[0]), "r"(a[1]), "r"(a[2]), "r"(a[3]), "r"(b0), "r"(b1));
}

__device__ __forceinline__ void cvt_pair8(const float* v, uint4& hi, uint4& lo) {
    unsigned hs[8], ls[8];
    #pragma unroll
    for (int j = 0; j < 8; ++j) {
        __nv_bfloat16 h = __float2bfloat16(v[j]);
        float hf = __bfloat162float(h);
        __nv_bfloat16 l = __float2bfloat16(v[j] - hf);
        hs[j] = (unsigned)__bfloat16_as_ushort(h);
        ls[j] = (unsigned)__bfloat16_as_ushort(l);
    }
    hi.x = hs[0] | (hs[1] << 16); hi.y = hs[2] | (hs[3] << 16);
    hi.z = hs[4] | (hs[5] << 16); hi.w = hs[6] | (hs[7] << 16);
    lo.x = ls[0] | (ls[1] << 16); lo.y = ls[2] | (ls[3] << 16);
    lo.z = ls[4] | (ls[5] << 16); lo.w = ls[6] | (ls[7] << 16);
}
__device__ __forceinline__ void cvt_pair4(float4 v, uint2& hi, uint2& lo) {
    float f[4] = {v.x, v.y, v.z, v.w};
    unsigned hs[4], ls[4];
    #pragma unroll
    for (int j = 0; j < 4; ++j) {
        __nv_bfloat16 h = __float2bfloat16(f[j]);
        float hf = __bfloat162float(h);
        __nv_bfloat16 l = __float2bfloat16(f[j] - hf);
        hs[j] = (unsigned)__bfloat16_as_ushort(h);
        ls[j] = (unsigned)__bfloat16_as_ushort(l);
    }
    hi.x = hs[0] | (hs[1] << 16); hi.y = hs[2] | (hs[3] << 16);
    lo.x = ls[0] | (ls[1] << 16); lo.y = ls[2] | (ls[3] << 16);
}

// ================= input-projection GEMM on HMMA (layer 0, validated) =================
constexpr int GM_THREADS = 256;
constexpr int PITCH = 80;
constexpr int PLANE = 128 * PITCH;
constexpr int SB_BIAS = 0;
constexpr int SB_AH = 1024;
constexpr int SB_AL = SB_AH + PLANE;
constexpr int SB_BH = SB_AL + PLANE;
constexpr int SB_BL = SB_BH + PLANE;
constexpr size_t GM_SMEM = SB_BL + PLANE;

template<int K>
__global__ void __launch_bounds__(GM_THREADS)
gemm_mma(const float* __restrict__ A, const float* __restrict__ W,
         const float* __restrict__ b1, const float* __restrict__ b2,
         float* __restrict__ Cout)
{
    extern __shared__ char sm[];
    const uint32_t sbase = smem_u32(sm);
    float* sbias = (float*)(sm + SB_BIAS);

    const int tid  = threadIdx.x;
    const int lane = tid & 31;
    const int warp = tid >> 5;
    const int wm   = warp >> 2;
    const int wn   = warp & 3;
    const int n0   = blockIdx.x * 128;
    const size_t m0 = (size_t)blockIdx.y * 128;

    if (tid < 128) sbias[tid] = b1[n0 + tid] + b2[n0 + tid];

    const int lrow  = tid >> 1;
    const int lhalf = tid & 1;
    const float* gA = A + (m0 + lrow) * K + lhalf * 16;
    const float* gB = W + (size_t)(n0 + lrow) * K + lhalf * 16;

    float acc[4][4][4] = {};
    float ra[16], rb[16];

    #pragma unroll
    for (int q = 0; q < 4; ++q) {
        *(float4*)(ra + q * 4) = *(const float4*)(gA + q * 4);
        *(float4*)(rb + q * 4) = *(const float4*)(gB + q * 4);
    }

    constexpr int NC = K / 32;
    for (int c = 0; c < NC; ++c) {
        #pragma unroll
        for (int j = 0; j < 2; ++j) {
            uint4 hi, lo;
            uint32_t off = (uint32_t)(lrow * PITCH + lhalf * 32 + j * 16);
            cvt_pair8(ra + j * 8, hi, lo);
            *(uint4*)(sm + SB_AH + off) = hi;
            *(uint4*)(sm + SB_AL + off) = lo;
            cvt_pair8(rb + j * 8, hi, lo);
            *(uint4*)(sm + SB_BH + off) = hi;
            *(uint4*)(sm + SB_BL + off) = lo;
        }
        __syncthreads();

        if (c + 1 < NC) {
            #pragma unroll
            for (int q = 0; q < 4; ++q) {
                *(float4*)(ra + q * 4) = *(const float4*)(gA + (c + 1) * 32 + q * 4);
                *(float4*)(rb + q * 4) = *(const float4*)(gB + (c + 1) * 32 + q * 4);
            }
        }

        #pragma unroll
        for (int kb = 0; kb < 2; ++kb) {
            uint32_t Ah[4][4], Al[4][4], Bh[2][4], Bl[2][4];
            const uint32_t acol = (uint32_t)(kb * 32 + (lane >> 4) * 16);
            #pragma unroll
            for (int mi = 0; mi < 4; ++mi) {
                uint32_t rowoff = (uint32_t)((wm * 64 + mi * 16 + (lane & 15)) * PITCH) + acol;
                ldmx4(Ah[mi], sbase + SB_AH + rowoff);
                ldmx4(Al[mi], sbase + SB_AL + rowoff);
            }
            const uint32_t bcol = (uint32_t)(kb * 32 + ((lane >> 3) & 1) * 16);
            #pragma unroll
            for (int nb = 0; nb < 2; ++nb) {
                uint32_t rowoff = (uint32_t)((wn * 32 + nb * 16 + (lane & 7) + ((lane >> 4) << 3)) * PITCH) + bcol;
                ldmx4(Bh[nb], sbase + SB_BH + rowoff);
                ldmx4(Bl[nb], sbase + SB_BL + rowoff);
            }
            #pragma unroll
            for (int mi = 0; mi < 4; ++mi) {
                #pragma unroll
                for (int ni = 0; ni < 4; ++ni) {
                    const int nb = ni >> 1, h = (ni & 1) * 2;
                    mma16816(acc[mi][ni], Ah[mi], Bh[nb][h], Bh[nb][h + 1]);
                    mma16816(acc[mi][ni], Ah[mi], Bl[nb][h], Bl[nb][h + 1]);
                    mma16816(acc[mi][ni], Al[mi], Bh[nb][h], Bh[nb][h + 1]);
                }
            }
        }
        __syncthreads();
    }

    const int g   = lane >> 2;
    const int tig = lane & 3;
    #pragma unroll
    for (int mi = 0; mi < 4; ++mi) {
        const size_t row = m0 + wm * 64 + mi * 16 + g;
        float* dst0 = Cout + row * G4H + n0;
        float* dst8 = dst0 + (size_t)8 * G4H;
        #pragma unroll
        for (int ni = 0; ni < 4; ++ni) {
            const int col = wn * 32 + ni * 8 + tig * 2;
            const float bb0 = sbias[col], bb1 = sbias[col + 1];
            float2 v0 = {acc[mi][ni][0] + bb0, acc[mi][ni][1] + bb1};
            float2 v1 = {acc[mi][ni][2] + bb0, acc[mi][ni][3] + bb1};
            *(float2*)(dst0 + col) = v0;
            *(float2*)(dst8 + col) = v1;
        }
    }
}

// ================= per-row-group barrier (16 CTAs) =================
__device__ __forceinline__ void group_sync(int grp)
{
    __syncthreads();
    if (threadIdx.x == 0) {
        __threadfence();
        unsigned int gen  = *((volatile unsigned int*)&g_grp_gen[grp][0]);
        unsigned int prev = atomicAdd(&g_grp_count[grp][0], 1u);
        if (prev == GROUP_CTAS - 1) {
            g_grp_count[grp][0] = 0;
            __threadfence();
            atomicAdd(&g_grp_gen[grp][0], 1u);
        } else {
            while (*((volatile unsigned int*)&g_grp_gen[grp][0]) == gen) { }
            __threadfence();
        }
    }
    __syncthreads();
}

__device__ __forceinline__ float sigmoidf_(float x) { return 1.0f / (1.0f + __expf(-x)); }

// ================= persistent LSTM recurrence, warp-specialized ========
// CTA(bi,bu): rows [bi*32,+32), units [bu*16,+16). 8 warps.
// FUSED:  warps 0-3 = gate GEMM (full K), warps 4-7 = next-layer projection (full K).
// !FUSED: warps 0-3 = gates K-blocks 0-7, warps 4-7 = gates K-blocks 8-15 (2 Gs planes).
constexpr int RPITCH  = 528;
constexpr int R_WH_HI = 0;                          // 64 rows
constexpr int R_WH_LO = R_WH_HI + 64 * RPITCH;      // 33792
constexpr int R_WN_HI = R_WH_LO + 64 * RPITCH;      // 67584
constexpr int R_WN_LO = R_WN_HI + 64 * RPITCH;      // 101376
constexpr int R_AH    = R_WN_LO + 64 * RPITCH;      // 135168 (32 rows)
constexpr int R_AL    = R_AH + 32 * RPITCH;         // 152064
constexpr int R_GS    = R_AL + 32 * RPITCH;         // 168960: TWO planes of 32x66 floats
constexpr int GS_PLANE = 32 * 66;                   // floats per plane
constexpr int R_CS    = R_GS + 2 * GS_PLANE * 4;    // 185856 (32 x 17 floats)
constexpr int R_BN    = R_CS + 32 * 17 * 4;         // 188032 (64 floats)
constexpr size_t R_SMEM = (size_t)R_BN + 64 * 4;    // 188288 B

__device__ __forceinline__ void load_h_tile(char* smr, const __nv_bfloat16* hhi,
                                            const __nv_bfloat16* hlo, int r0, int tid)
{
    #pragma unroll
    for (int it = 0; it < 4; ++it) {
        int idx = tid + it * THREADS_R;   // 0..1023 chunks of 16B
        int row = idx >> 5, ch = idx & 31;
        uint4 v = __ldcg((const uint4*)(hhi + (r0 + row) * HID) + ch);
        *(uint4*)(smr + R_AH + row * RPITCH + ch * 16) = v;
        v = __ldcg((const uint4*)(hlo + (r0 + row) * HID) + ch);
        *(uint4*)(smr + R_AL + row * RPITCH + ch * 16) = v;
    }
}

// MMA over A planes vs a weight plane pair, K-blocks [kb0, kb1), gate column g4.
__device__ __forceinline__ void pair_mma(const uint32_t sbase, int lane, int g4,
                                         int kb0, int kb1, int whi, int wlo,
                                         float acc[2][2][4])
{
    for (int kb = kb0; kb < kb1; ++kb) {
        uint32_t Ahf[2][4], Alf[2][4], Bhf[4], Blf[4];
        const uint32_t acol = (uint32_t)(kb * 32 + (lane >> 4) * 16);
        #pragma unroll
        for (int mi = 0; mi < 2; ++mi) {
            uint32_t ro = (uint32_t)((mi * 16 + (lane & 15)) * RPITCH) + acol;
            ldmx4(Ahf[mi], sbase + R_AH + ro);
            ldmx4(Alf[mi], sbase + R_AL + ro);
        }
        const uint32_t brow = (uint32_t)(g4 * 16 + (lane & 7) + ((lane >> 4) << 3));
        const uint32_t bcol = (uint32_t)(kb * 32 + ((lane >> 3) & 1) * 16);
        ldmx4(Bhf, sbase + whi + brow * RPITCH + bcol);
        ldmx4(Blf, sbase + wlo + brow * RPITCH + bcol);
        #pragma unroll
        for (int mi = 0; mi < 2; ++mi)
            #pragma unroll
            for (int ni = 0; ni < 2; ++ni) {
                const int h2 = ni * 2;
                mma16816(acc[mi][ni], Ahf[mi], Bhf[h2], Bhf[h2 + 1]);
                mma16816(acc[mi][ni], Ahf[mi], Blf[h2], Blf[h2 + 1]);
                mma16816(acc[mi][ni], Alf[mi], Bhf[h2], Bhf[h2 + 1]);
            }
    }
}

__device__ __forceinline__ void proj_store(float* __restrict__ xpre_out, const float* sbn,
                                           float acc2[2][2][4], int t_store,
                                           int r0, int u0, int g4, int gq, int tig)
{
    #pragma unroll
    for (int mi = 0; mi < 2; ++mi) {
        const int row = r0 + mi * 16 + gq;
        float* d0 = xpre_out + ((size_t)row * SEQ + t_store) * G4H + g4 * HID + u0;
        float* d8 = xpre_out + ((size_t)(row + 8) * SEQ + t_store) * G4H + g4 * HID + u0;
        #pragma unroll
        for (int ni = 0; ni < 2; ++ni) {
            const int uu = ni * 8 + tig * 2;
            const float b0 = sbn[g4 * 16 + uu], b1v = sbn[g4 * 16 + uu + 1];
            float2 v0 = {acc2[mi][ni][0] + b0, acc2[mi][ni][1] + b1v};
            float2 v1 = {acc2[mi][ni][2] + b0, acc2[mi][ni][3] + b1v};
            *(float2*)(d0 + uu) = v0;
            *(float2*)(d8 + uu) = v1;
        }
    }
}

template<bool FUSED>
__global__ void __launch_bounds__(THREADS_R, 1)
lstm_layer_kernel(const float* __restrict__ Whh,
                  const float* __restrict__ xpre_in,
                  const float* __restrict__ Wih_next,
                  const float* __restrict__ bn1,
                  const float* __restrict__ bn2,
                  float* __restrict__ xpre_out,
                  float* __restrict__ y_out,
                  float* __restrict__ out_h,
                  float* __restrict__ out_c)
{
    extern __shared__ char smr[];
    const uint32_t sbase = smem_u32(smr);
    float* Gs0 = (float*)(smr + R_GS);
    float* Gs1 = Gs0 + GS_PLANE;
    float* Cs  = (float*)(smr + R_CS);
    float* sbn = (float*)(smr + R_BN);

    const int tid  = threadIdx.x;
    const int lane = tid & 31;
    const int w    = tid >> 5;          // warp 0..7
    const int g4w  = w & 3;             // gate index within role
    const int role = w >> 2;            // 0: gates / low-K, 1: proj / high-K
    const int bi   = blockIdx.x >> 4;
    const int bu   = blockIdx.x & 15;
    const int r0   = bi * 32;
    const int u0   = bu * 16;

    // ---- prologue: weights -> bf16-pair SMEM planes ----
    #pragma unroll 4
    for (int it = 0; it < 16; ++it) {
        int idx = tid + it * THREADS_R;      // 0..4095 float4s
        int cc  = idx >> 6;
        int kf  = idx & 63;
        int g4  = cc >> 4, uu = cc & 15;
        float4 v = *(const float4*)(&Whh[(size_t)(g4 * HID + u0 + uu) * HID + kf * 4]);
        uint2 hi, lo; cvt_pair4(v, hi, lo);
        *(uint2*)(smr + R_WH_HI + cc * RPITCH + kf * 8) = hi;
        *(uint2*)(smr + R_WH_LO + cc * RPITCH + kf * 8) = lo;
    }
    if (FUSED) {
        #pragma unroll 4
        for (int it = 0; it < 16; ++it) {
            int idx = tid + it * THREADS_R;
            int cc  = idx >> 6;
            int kf  = idx & 63;
            int g4  = cc >> 4, uu = cc & 15;
            float4 v = *(const float4*)(&Wih_next[(size_t)(g4 * HID + u0 + uu) * HID + kf * 4]);
            uint2 hi, lo; cvt_pair4(v, hi, lo);
            *(uint2*)(smr + R_WN_HI + cc * RPITCH + kf * 8) = hi;
            *(uint2*)(smr + R_WN_LO + cc * RPITCH + kf * 8) = lo;
        }
        if (tid < 64) {
            int g4 = tid >> 4, uu = tid & 15;
            sbn[tid] = bn1[g4 * HID + u0 + uu] + bn2[g4 * HID + u0 + uu];
        }
    }
    for (int q = tid; q < 512; q += THREADS_R) {
        int r = q & 31, uu = q >> 5;
        g_hbf[0][0][(r0 + r) * HID + u0 + uu] = __float2bfloat16(0.0f);
        g_hbf[0][1][(r0 + r) * HID + u0 + uu] = __float2bfloat16(0.0f);
    }
    for (int q = tid; q < 32 * 17; q += THREADS_R) Cs[q] = 0.0f;
    group_sync(bi);

    const int gq  = lane >> 2;          // C-fragment row group
    const int tig = lane & 3;
    const int row_a = lane;             // activation row (0..31)
    // activation: thread (w, lane) owns row=lane, units w*2 .. w*2+1

    const float* xp_base = xpre_in + ((size_t)(r0 + row_a) * SEQ) * G4H + u0 + w * 2;

    // prefetch xpre for t=0 (float2 per gate)
    float xv[4][2];
    #pragma unroll
    for (int g4 = 0; g4 < 4; ++g4) {
        float2 f = *(const float2*)(xp_base + (size_t)g4 * HID);
        xv[g4][0] = f.x; xv[g4][1] = f.y;
    }

    int cur = 0;
    for (int t = 0; t < SEQ; ++t) {
        load_h_tile(smr, g_hbf[cur][0], g_hbf[cur][1], r0, tid);
        __syncthreads();

        if (FUSED) {
            if (role == 0) {
                // gate warps: full-K gate GEMM
                float acc[2][2][4] = {};
                pair_mma(sbase, lane, g4w, 0, 16, R_WH_HI, R_WH_LO, acc);
                #pragma unroll
                for (int mi = 0; mi < 2; ++mi)
                    #pragma unroll
                    for (int ni = 0; ni < 2; ++ni) {
                        const int col = g4w * 16 + ni * 8 + tig * 2;
                        *(float2*)(&Gs0[(mi * 16 + gq) * 66 + col])     = make_float2(acc[mi][ni][0], acc[mi][ni][1]);
                        *(float2*)(&Gs0[(mi * 16 + gq + 8) * 66 + col]) = make_float2(acc[mi][ni][2], acc[mi][ni][3]);
                    }
            } else {
                // proj warps: full-K projection GEMM, store straight to xpre_out
                float acc2[2][2][4] = {};
                pair_mma(sbase, lane, g4w, 0, 16, R_WN_HI, R_WN_LO, acc2);
                if (t > 0)
                    proj_store(xpre_out, sbn, acc2, t - 1, r0, u0, g4w, gq, tig);
            }
        } else {
            // split-K gates: role 0 -> kb 0..8, role 1 -> kb 8..16
            float acc[2][2][4] = {};
            pair_mma(sbase, lane, g4w, role * 8, role * 8 + 8, R_WH_HI, R_WH_LO, acc);
            float* Gp = role == 0 ? Gs0 : Gs1;
            #pragma unroll
            for (int mi = 0; mi < 2; ++mi)
                #pragma unroll
                for (int ni = 0; ni < 2; ++ni) {
                    const int col = g4w * 16 + ni * 8 + tig * 2;
                    *(float2*)(&Gp[(mi * 16 + gq) * 66 + col])     = make_float2(acc[mi][ni][0], acc[mi][ni][1]);
                    *(float2*)(&Gp[(mi * 16 + gq + 8) * 66 + col]) = make_float2(acc[mi][ni][2], acc[mi][ni][3]);
                }
        }
        __syncthreads();

        // ---- activations: thread owns (row_a, units w*2..+1) ----
        __nv_bfloat16* dhi = g_hbf[cur ^ 1][0];
        __nv_bfloat16* dlo = g_hbf[cur ^ 1][1];
        unsigned hh[2], hl[2];
        float2 yv, cv;
        float* ys  = (float*)&yv;
        float* cs2 = (float*)&cv;
        #pragma unroll
        for (int j = 0; j < 2; ++j) {
            int uu = w * 2 + j;
            float gi, gf, gg, go;
            if (FUSED) {
                gi = Gs0[row_a * 66 +      uu];
                gf = Gs0[row_a * 66 + 16 + uu];
                gg = Gs0[row_a * 66 + 32 + uu];
                go = Gs0[row_a * 66 + 48 + uu];
            } else {
                gi = Gs0[row_a * 66 +      uu] + Gs1[row_a * 66 +      uu];
                gf = Gs0[row_a * 66 + 16 + uu] + Gs1[row_a * 66 + 16 + uu];
                gg = Gs0[row_a * 66 + 32 + uu] + Gs1[row_a * 66 + 32 + uu];
                go = Gs0[row_a * 66 + 48 + uu] + Gs1[row_a * 66 + 48 + uu];
            }
            gi += xv[0][j]; gf += xv[1][j]; gg += xv[2][j]; go += xv[3][j];
            float ig = sigmoidf_(gi);
            float fg = sigmoidf_(gf);
            float og = sigmoidf_(go);
            float gc = tanhf(gg);
            float c  = fg * Cs[row_a * 17 + uu] + ig * gc;
            float h  = og * tanhf(c);
            Cs[row_a * 17 + uu] = c;
            __nv_bfloat16 hb = __float2bfloat16(h);
            float hf = __bfloat162float(hb);
            __nv_bfloat16 lb = __float2bfloat16(h - hf);
            hh[j] = (unsigned)__bfloat16_as_ushort(hb);
            hl[j] = (unsigned)__bfloat16_as_ushort(lb);
            ys[j] = h;
            cs2[j] = c;
        }
        {
            const int uoff = (r0 + row_a) * HID + u0 + w * 2;
            *(unsigned*)(dhi + uoff) = hh[0] | (hh[1] << 16);
            *(unsigned*)(dlo + uoff) = hl[0] | (hl[1] << 16);
            if (y_out != nullptr)
                *(float2*)(&y_out[((size_t)(r0 + row_a) * SEQ + t) * HID + u0 + w * 2]) = yv;
            if (out_h != nullptr && t == SEQ - 1) {
                *(float2*)(&out_h[uoff]) = yv;
                *(float2*)(&out_c[uoff]) = cv;
            }
        }

        // ---- prefetch next step's xpre before the barrier ----
        if (t + 1 < SEQ) {
            const float* xp = xp_base + (size_t)(t + 1) * G4H;
            #pragma unroll
            for (int g4 = 0; g4 < 4; ++g4) {
                float2 f = *(const float2*)(xp + (size_t)g4 * HID);
                xv[g4][0] = f.x; xv[g4][1] = f.y;
            }
        }

        group_sync(bi);
        cur ^= 1;
    }

    // ---- epilogue (FUSED): project h_{SEQ-1} -> xpre_out[:, SEQ-1] ----
    if (FUSED) {
        load_h_tile(smr, g_hbf[cur][0], g_hbf[cur][1], r0, tid);
        __syncthreads();
        if (role == 1) {
            float acc2[2][2][4] = {};
            pair_mma(sbase, lane, g4w, 0, 16, R_WN_HI, R_WN_LO, acc2);
            proj_store(xpre_out, sbn, acc2, SEQ - 1, r0, u0, g4w, gq, tig);
        }
    }
}

// ================= launch =================
extern "C" void kernel_launch(void* const* d_in, const int* in_sizes, int n_in,
                              void* d_out, int out_size)
{
    const float* x    = (const float*)d_in[0];
    const float* Wih0 = (const float*)d_in[1];
    const float* Whh0 = (const float*)d_in[2];
    const float* bih0 = (const float*)d_in[3];
    const float* bhh0 = (const float*)d_in[4];
    const float* Wih1 = (const float*)d_in[5];
    const float* Whh1 = (const float*)d_in[6];
    const float* bih1 = (const float*)d_in[7];
    const float* bhh1 = (const float*)d_in[8];
    float* out = (float*)d_out;

    float* xpre0 = nullptr;
    float* xpre1 = nullptr;
    cudaGetSymbolAddress((void**)&xpre0, g_xpre0);
    cudaGetSymbolAddress((void**)&xpre1, g_xpre1);

    cudaFuncSetAttribute(lstm_layer_kernel<true>,
                         cudaFuncAttributeMaxDynamicSharedMemorySize, (int)R_SMEM);
    cudaFuncSetAttribute(lstm_layer_kernel<false>,
                         cudaFuncAttributeMaxDynamicSharedMemorySize, (int)R_SMEM);
    cudaFuncSetAttribute(gemm_mma<INP>,
                         cudaFuncAttributeMaxDynamicSharedMemorySize, (int)GM_SMEM);

    dim3 tgrid(G4H / 128, (BATCH * SEQ) / 128);   // (8, 1024)

    // Layer 0: input projection, then recurrence with warp-specialized fused layer-1 projection
    gemm_mma<INP><<<tgrid, GM_THREADS, GM_SMEM>>>(x, Wih0, bih0, bhh0, xpre0);
    lstm_layer_kernel<true><<<GRID_P, THREADS_R, R_SMEM>>>(
        Whh0, xpre0, Wih1, bih1, bhh1, xpre1, nullptr, nullptr, nullptr);

    // Layer 1: recurrence only, split-K across the 8 warps
    float* out_h = out + (size_t)BATCH * SEQ * HID;
    float* out_c = out_h + (size_t)BATCH * HID;
    lstm_layer_kernel<false><<<GRID_P, THREADS_R, R_SMEM>>>(
        Whh1, xpre1, nullptr, nullptr, nullptr, nullptr, out, out_h, out_c);
}